// round 5
// baseline (speedup 1.0000x reference)
#include <cuda_runtime.h>
#include <cuda_fp16.h>
#include <math.h>
#include <float.h>
#include <cstdint>

// Problem constants
#define T_SEQ 2048
#define HID   4096
#define NH    16
#define DH    256
#define QKV_N (3 * NH * DH)      // 12288
#define Q_SIZE (NH * DH)         // 4096
#define EPS   1e-6f
#define LN_THETA 9.210340371976184f   // ln(10000)

// GEMM tile config (fp16 engine): CTA 128x256, warp 64x64, 8 warps
#define BM 128
#define BN 256
#define BK 32                       // halfs per K-chunk
#define STRIDE 40                   // halfs per smem row (32 data + 8 pad)
#define STAGES 4
#define STAGE_BYTES ((BM + BN) * STRIDE * 2)   // 30720
#define SMEM_BYTES (STAGES * STAGE_BYTES)      // 122880

// ---------------------------------------------------------------------------
// Scratch (static device globals)
// ---------------------------------------------------------------------------
__device__ __half g_hidden_h[(size_t)T_SEQ * HID];          // 16 MB
__device__ __half g_wqkv_h[(size_t)QKV_N * HID];            // 96 MB (transposed)
__device__ __half g_wo_h[(size_t)HID * Q_SIZE];             // 32 MB (transposed)
__device__ float  g_qkv[(size_t)T_SEQ * QKV_N];             // 96 MB
__device__ __half g_qh[(size_t)T_SEQ * NH * DH];            // 16 MB
__device__ __half g_kh[(size_t)T_SEQ * NH * DH];            // 16 MB
__device__ __half g_vh[(size_t)T_SEQ * NH * DH];            // 16 MB
__device__ __half g_vth[(size_t)NH * DH * T_SEQ];           // 16 MB
__device__ float  g_scores[(size_t)NH * T_SEQ * T_SEQ];     // 256 MB
__device__ __half g_probs[(size_t)NH * T_SEQ * T_SEQ];      // 128 MB
__device__ __half g_attn_h[(size_t)T_SEQ * NH * DH];        // 16 MB

// ---------------------------------------------------------------------------
// PTX helpers (sm_75/80 baseline features only)
// ---------------------------------------------------------------------------
__device__ __forceinline__ uint32_t smem_u32(const void* p) {
    uint32_t a;
    asm("{ .reg .u64 t; cvta.to.shared.u64 t, %1; cvt.u32.u64 %0, t; }" : "=r"(a) : "l"(p));
    return a;
}
#define CP_ASYNC16(dst, src) \
    asm volatile("cp.async.cg.shared.global [%0], [%1], 16;" :: "r"(dst), "l"(src))
#define CP_COMMIT() asm volatile("cp.async.commit_group;" ::: "memory")
#define CP_WAIT(n)  asm volatile("cp.async.wait_group %0;" :: "n"(n) : "memory")

__device__ __forceinline__ void ldmx4(uint32_t* r, uint32_t addr) {
    asm volatile("ldmatrix.sync.aligned.m8n8.x4.shared.b16 {%0,%1,%2,%3}, [%4];"
        : "=r"(r[0]), "=r"(r[1]), "=r"(r[2]), "=r"(r[3]) : "r"(addr));
}
__device__ __forceinline__ void mma_f16(float* d, const uint32_t* a, const uint32_t* b) {
    asm volatile(
        "mma.sync.aligned.m16n8k16.row.col.f32.f16.f16.f32 "
        "{%0,%1,%2,%3}, {%4,%5,%6,%7}, {%8,%9}, {%0,%1,%2,%3};"
        : "+f"(d[0]), "+f"(d[1]), "+f"(d[2]), "+f"(d[3])
        : "r"(a[0]), "r"(a[1]), "r"(a[2]), "r"(a[3]), "r"(b[0]), "r"(b[1]));
}

// ---------------------------------------------------------------------------
// fp16 mma.sync batched GEMM: C[M,N](f32 or f16) = A[M,K] * B[N,K]^T
//   A, B __half row-major K-contiguous. CTA 128x256, warp tile 64x64.
// ---------------------------------------------------------------------------
template<bool CSKIP, bool CKLIM, bool HALF_OUT>
__global__ __launch_bounds__(256, 1)
void h_gemm(const __half* __restrict__ A, const __half* __restrict__ B, void* __restrict__ Cv,
            int M, int N, int K, int lda, int ldb, int ldc,
            long long bA, long long bB, long long bC)
{
    const int row0 = blockIdx.y * BM;
    const int col0 = blockIdx.x * BN;
    if (CSKIP && col0 >= row0 + BM) return;
    const int Keff = CKLIM ? min(K, row0 + BM) : K;
    const int nCh = Keff / BK;

    A += (long long)blockIdx.z * bA;
    B += (long long)blockIdx.z * bB;

    extern __shared__ char smem[];
    const uint32_t sbase = smem_u32(smem);

    const int tid = threadIdx.x;
    const int wid = tid >> 5, lane = tid & 31;
    const int g = lane >> 2, t4 = lane & 3;
    const int warpM = (wid & 1) * 64;             // 2 warp rows x 64
    const int warpN = (wid >> 1) * 64;            // 4 warp cols x 64
    const int lrow = lane & 7, lsel = lane >> 3;

    // per-lane ldmatrix byte offsets within a stage
    const uint32_t aoff = ((warpM + (lsel & 1) * 8 + lrow) * STRIDE + (lsel >> 1) * 8) * 2;
    const uint32_t boff = ((warpN + (lsel >> 1) * 8 + lrow) * STRIDE + (lsel & 1) * 8) * 2;

    float acc[4][8][4];
    #pragma unroll
    for (int i = 0; i < 4; i++)
        #pragma unroll
        for (int j = 0; j < 8; j++)
            #pragma unroll
            for (int q = 0; q < 4; q++) acc[i][j][q] = 0.0f;

    // loader: A tile 128x32 halfs (512 x 16B, 2/thread), B tile 256x32 (1024 x 16B, 4/thread)
    auto load_stage = [&](int st, int ch) {
        const uint32_t sA = sbase + st * STAGE_BYTES;
        const uint32_t sB = sA + BM * STRIDE * 2;
        const int k0 = ch * BK;
        #pragma unroll
        for (int i = 0; i < 2; i++) {
            int u = tid + i * 256;
            int r = u >> 2, cu = u & 3;
            CP_ASYNC16(sA + (r * STRIDE + cu * 8) * 2,
                       &A[(size_t)(row0 + r) * lda + k0 + cu * 8]);
        }
        #pragma unroll
        for (int i = 0; i < 4; i++) {
            int u = tid + i * 256;
            int r = u >> 2, cu = u & 3;
            CP_ASYNC16(sB + (r * STRIDE + cu * 8) * 2,
                       &B[(size_t)(col0 + r) * ldb + k0 + cu * 8]);
        }
    };

    // prologue: stages 0..STAGES-2
    #pragma unroll
    for (int p = 0; p < STAGES - 1; ++p) {
        if (p < nCh) load_stage(p, p);
        CP_COMMIT();
    }

    for (int c = 0; c < nCh; ++c) {
        if (c + STAGES - 1 < nCh) load_stage((c + STAGES - 1) % STAGES, c + STAGES - 1);
        CP_COMMIT();
        CP_WAIT(STAGES - 1);
        __syncthreads();

        const uint32_t sA = sbase + (c % STAGES) * STAGE_BYTES;
        const uint32_t sB = sA + BM * STRIDE * 2;

        #pragma unroll
        for (int kk = 0; kk < 2; ++kk) {          // two k16 steps per chunk
            uint32_t a[4][4];
            #pragma unroll
            for (int mt = 0; mt < 4; ++mt)
                ldmx4(a[mt], sA + aoff + mt * 16 * STRIDE * 2 + kk * 32);
            uint32_t b[8][2];
            #pragma unroll
            for (int j = 0; j < 4; ++j) {
                uint32_t r[4];
                ldmx4(r, sB + boff + j * 16 * STRIDE * 2 + kk * 32);
                b[2 * j][0] = r[0]; b[2 * j][1] = r[1];
                b[2 * j + 1][0] = r[2]; b[2 * j + 1][1] = r[3];
            }
            #pragma unroll
            for (int mt = 0; mt < 4; ++mt)
                #pragma unroll
                for (int nt = 0; nt < 8; ++nt)
                    mma_f16(acc[mt][nt], a[mt], b[nt]);
        }
        __syncthreads();
    }

    // epilogue
    #pragma unroll
    for (int mt = 0; mt < 4; mt++) {
        const int r0 = row0 + warpM + mt * 16 + g;
        #pragma unroll
        for (int nt = 0; nt < 8; nt++) {
            const int cc = col0 + warpN + nt * 8 + t4 * 2;
            if (HALF_OUT) {
                __half* C = (__half*)Cv + (long long)blockIdx.z * bC;
                *(__half2*)&C[(size_t)r0 * ldc + cc] =
                    __floats2half2_rn(acc[mt][nt][0], acc[mt][nt][1]);
                *(__half2*)&C[(size_t)(r0 + 8) * ldc + cc] =
                    __floats2half2_rn(acc[mt][nt][2], acc[mt][nt][3]);
            } else {
                float* C = (float*)Cv + (long long)blockIdx.z * bC;
                *(float2*)&C[(size_t)r0 * ldc + cc]       = make_float2(acc[mt][nt][0], acc[mt][nt][1]);
                *(float2*)&C[(size_t)(r0 + 8) * ldc + cc] = make_float2(acc[mt][nt][2], acc[mt][nt][3]);
            }
        }
    }
}

// ---------------------------------------------------------------------------
// Elementwise fp32 -> fp16 convert
// ---------------------------------------------------------------------------
__global__ __launch_bounds__(256)
void convert_h_kernel(const float* __restrict__ in, __half* __restrict__ out, int n)
{
    int i = (blockIdx.x * 256 + threadIdx.x) * 4;
    if (i < n) {
        float4 v = *(const float4*)&in[i];
        __half2 a = __floats2half2_rn(v.x, v.y);
        __half2 b = __floats2half2_rn(v.z, v.w);
        *(__half2*)&out[i]     = a;
        *(__half2*)&out[i + 2] = b;
    }
}

// ---------------------------------------------------------------------------
// Tiled transpose with type conversion: out[C,R] = (Tout)in[R,C]^T
// ---------------------------------------------------------------------------
template<typename Tin, typename Tout>
__global__ __launch_bounds__(256)
void transpose_kernel(const Tin* __restrict__ in, Tout* __restrict__ out, int R, int C)
{
    __shared__ float tile[32][33];
    const int c0 = blockIdx.x * 32, r0 = blockIdx.y * 32;
    const int x = threadIdx.x, y = threadIdx.y;    // block (32, 8)
    #pragma unroll
    for (int i = 0; i < 32; i += 8)
        tile[y + i][x] = (float)in[(size_t)(r0 + y + i) * C + c0 + x];
    __syncthreads();
    #pragma unroll
    for (int i = 0; i < 32; i += 8)
        out[(size_t)(c0 + y + i) * R + r0 + x] = (Tout)tile[x][y + i];
}

// ---------------------------------------------------------------------------
// Fused RMSNorm + NeoX RoPE -> fp16 q/k/v
// ---------------------------------------------------------------------------
__global__ __launch_bounds__(256)
void normrope_kernel(const float* __restrict__ qkv,
                     const int*   __restrict__ positions,
                     const float* __restrict__ qw,
                     const float* __restrict__ kw,
                     __half* __restrict__ q_out,
                     __half* __restrict__ k_out,
                     __half* __restrict__ v_out)
{
    const int h = blockIdx.x;
    const int t = blockIdx.y;
    const int d = threadIdx.x;

    __shared__ float red[256];
    __shared__ float xn[256];

    const int pos = positions[t];
    const size_t row = (size_t)t * QKV_N;
    const size_t out_idx = (size_t)t * (NH * DH) + (size_t)h * DH + d;

    const int fi = d & 127;
    const float inv_freq = expf(-(float)fi * (LN_THETA / 128.0f));
    const float ang = (float)pos * inv_freq;
    const float c = cosf(ang);
    const float s = sinf(ang);

    #pragma unroll
    for (int sec = 0; sec < 3; sec++) {
        const int base = sec * Q_SIZE + h * DH;
        const float x = qkv[row + base + d];

        red[d] = x * x;
        __syncthreads();
        #pragma unroll
        for (int st = 128; st > 0; st >>= 1) {
            if (d < st) red[d] += red[d + st];
            __syncthreads();
        }
        const float rs = rsqrtf(red[0] / (float)DH + EPS);
        __syncthreads();

        float w = 1.0f;
        if (sec == 0) w = qw[d];
        else if (sec == 1) w = kw[d];
        float val = x * rs * w;

        if (sec < 2) {
            xn[d] = val;
            __syncthreads();
            float outv;
            if (d < 128) outv = xn[d] * c - xn[d + 128] * s;
            else         outv = xn[d] * c + xn[d - 128] * s;
            __syncthreads();
            if (sec == 0) q_out[out_idx] = __float2half(outv);
            else          k_out[out_idx] = __float2half(outv);
        } else {
            v_out[out_idx] = __float2half(val);
        }
    }
}

// ---------------------------------------------------------------------------
// Causal softmax: read fp32 scores, write fp16 probs (zero tail to block end)
// ---------------------------------------------------------------------------
__global__ __launch_bounds__(256)
void softmax_kernel(const float* __restrict__ S, __half* __restrict__ P)
{
    const int t = blockIdx.x;
    const int h = blockIdx.y;
    const float* row = S + ((size_t)h * T_SEQ + t) * T_SEQ;
    __half* prow = P + ((size_t)h * T_SEQ + t) * T_SEQ;
    const int L = t + 1;
    const int Lpad = ((t >> 7) + 1) << 7;     // round up to 128 (PV reads this far)
    const int tid = threadIdx.x;
    __shared__ float red[256];

    float m = -FLT_MAX;
    for (int s = tid; s < L; s += 256) m = fmaxf(m, row[s]);
    red[tid] = m;
    __syncthreads();
    #pragma unroll
    for (int st = 128; st > 0; st >>= 1) {
        if (tid < st) red[tid] = fmaxf(red[tid], red[tid + st]);
        __syncthreads();
    }
    m = red[0];
    __syncthreads();

    float sum = 0.0f;
    for (int s = tid; s < L; s += 256) sum += expf(row[s] - m);
    red[tid] = sum;
    __syncthreads();
    #pragma unroll
    for (int st = 128; st > 0; st >>= 1) {
        if (tid < st) red[tid] += red[tid + st];
        __syncthreads();
    }
    const float inv = 1.0f / red[0];
    __syncthreads();

    for (int s = tid; s < Lpad; s += 256)
        prow[s] = (s < L) ? __float2half(expf(row[s] - m) * inv) : __half(0.0f);
}

// ---------------------------------------------------------------------------
// Launch
// ---------------------------------------------------------------------------
extern "C" void kernel_launch(void* const* d_in, const int* in_sizes, int n_in,
                              void* d_out, int out_size)
{
    const float* hidden    = (const float*)d_in[0];
    const int*   positions = (const int*)  d_in[1];
    const float* w_qkv     = (const float*)d_in[2];
    const float* w_o       = (const float*)d_in[3];
    const float* qw        = (const float*)d_in[4];
    const float* kw        = (const float*)d_in[5];
    float* out = (float*)d_out;

    __half *hid_h, *wqkv_h, *wo_h, *qh, *kh, *vh, *vth, *probs, *attn_h;
    float *qkv, *sc;
    cudaGetSymbolAddress((void**)&hid_h,  g_hidden_h);
    cudaGetSymbolAddress((void**)&wqkv_h, g_wqkv_h);
    cudaGetSymbolAddress((void**)&wo_h,   g_wo_h);
    cudaGetSymbolAddress((void**)&qkv,    g_qkv);
    cudaGetSymbolAddress((void**)&qh,     g_qh);
    cudaGetSymbolAddress((void**)&kh,     g_kh);
    cudaGetSymbolAddress((void**)&vh,     g_vh);
    cudaGetSymbolAddress((void**)&vth,    g_vth);
    cudaGetSymbolAddress((void**)&sc,     g_scores);
    cudaGetSymbolAddress((void**)&probs,  g_probs);
    cudaGetSymbolAddress((void**)&attn_h, g_attn_h);

    cudaFuncSetAttribute(h_gemm<false, false, false>, cudaFuncAttributeMaxDynamicSharedMemorySize, SMEM_BYTES);
    cudaFuncSetAttribute(h_gemm<true,  false, false>, cudaFuncAttributeMaxDynamicSharedMemorySize, SMEM_BYTES);
    cudaFuncSetAttribute(h_gemm<false, true,  true >, cudaFuncAttributeMaxDynamicSharedMemorySize, SMEM_BYTES);

    // 0) operand conversions / transposes
    convert_h_kernel<<<(T_SEQ * HID / 4 + 255) / 256, 256>>>(hidden, hid_h, T_SEQ * HID);
    transpose_kernel<float, __half><<<dim3(QKV_N / 32, HID / 32), dim3(32, 8)>>>(w_qkv, wqkv_h, HID, QKV_N);
    transpose_kernel<float, __half><<<dim3(HID / 32,   HID / 32), dim3(32, 8)>>>(w_o,   wo_h,   HID, HID);

    // 1) qkv = hidden @ w_qkv  (fp32 out for exact rmsnorm)
    h_gemm<false, false, false><<<dim3(QKV_N / BN, T_SEQ / BM, 1), 256, SMEM_BYTES>>>(
        hid_h, wqkv_h, qkv, T_SEQ, QKV_N, HID, HID, HID, QKV_N, 0, 0, 0);

    // 2) rmsnorm + rope -> fp16 q/k/v
    normrope_kernel<<<dim3(NH, T_SEQ), 256>>>(qkv, positions, qw, kw, qh, kh, vh);

    // 2b) transpose V -> [NH*DH, T] fp16
    transpose_kernel<__half, __half><<<dim3((NH * DH) / 32, T_SEQ / 32), dim3(32, 8)>>>(vh, vth, T_SEQ, NH * DH);

    // 3) scores[h] = Q_h @ K_h^T (fp32 out, causal tile skip)
    h_gemm<true, false, false><<<dim3(T_SEQ / BN, T_SEQ / BM, NH), 256, SMEM_BYTES>>>(
        qh, kh, sc, T_SEQ, T_SEQ, DH,
        NH * DH, NH * DH, T_SEQ,
        DH, DH, (long long)T_SEQ * T_SEQ);

    // 4) causal softmax -> fp16 probs
    softmax_kernel<<<dim3(T_SEQ, NH), 256>>>(sc, probs);

    // 5) attn[h] = P_h @ V_h (fp16 out, causal K limit)
    h_gemm<false, true, true><<<dim3(DH / BN, T_SEQ / BM, NH), 256, SMEM_BYTES>>>(
        probs, vth, attn_h, T_SEQ, DH, T_SEQ,
        T_SEQ, T_SEQ, NH * DH,
        (long long)T_SEQ * T_SEQ, (long long)DH * T_SEQ, DH);

    // 6) out = attn @ w_o (fp32 out)
    h_gemm<false, false, false><<<dim3(HID / BN, T_SEQ / BM, 1), 256, SMEM_BYTES>>>(
        attn_h, wo_h, out, T_SEQ, HID, Q_SIZE, Q_SIZE, Q_SIZE, HID, 0, 0, 0);

    (void)in_sizes; (void)n_in; (void)out_size;
}

// round 6
// speedup vs baseline: 1.2752x; 1.2752x over previous
#include <cuda_runtime.h>
#include <cuda_fp16.h>
#include <math.h>
#include <float.h>
#include <cstdint>

// Problem constants
#define T_SEQ 2048
#define HID   4096
#define NH    16
#define DH    256
#define QKV_N (3 * NH * DH)      // 12288
#define Q_SIZE (NH * DH)         // 4096
#define EPS   1e-6f
#define LN_THETA 9.210340371976184f   // ln(10000)

// GEMM tile config (fp16 engine): CTA 128x128, warp 32x64, 8 warps, BK=64
#define BM 128
#define BN 128
#define BK 64                       // halfs per K-chunk
#define STRIDE 72                   // halfs per smem row (64 data + 8 pad)
#define STAGES 3
#define STAGE_BYTES ((BM + BN) * STRIDE * 2)   // 36864
#define SMEM_BYTES (STAGES * STAGE_BYTES)      // 110592

// ---------------------------------------------------------------------------
// Scratch (static device globals)
// ---------------------------------------------------------------------------
__device__ __half g_hidden_h[(size_t)T_SEQ * HID];          // 16 MB
__device__ __half g_wqkv_h[(size_t)QKV_N * HID];            // 96 MB (transposed)
__device__ __half g_wo_h[(size_t)HID * Q_SIZE];             // 32 MB (transposed)
__device__ float  g_qkv[(size_t)T_SEQ * QKV_N];             // 96 MB
__device__ __half g_qh[(size_t)T_SEQ * NH * DH];            // 16 MB
__device__ __half g_kh[(size_t)T_SEQ * NH * DH];            // 16 MB
__device__ __half g_vh[(size_t)T_SEQ * NH * DH];            // 16 MB
__device__ __half g_vth[(size_t)NH * DH * T_SEQ];           // 16 MB
__device__ float  g_scores[(size_t)NH * T_SEQ * T_SEQ];     // 256 MB
__device__ __half g_probs[(size_t)NH * T_SEQ * T_SEQ];      // 128 MB
__device__ __half g_attn_h[(size_t)T_SEQ * NH * DH];        // 16 MB

// ---------------------------------------------------------------------------
// PTX helpers (sm_75/80 baseline features only)
// ---------------------------------------------------------------------------
__device__ __forceinline__ uint32_t smem_u32(const void* p) {
    uint32_t a;
    asm("{ .reg .u64 t; cvta.to.shared.u64 t, %1; cvt.u32.u64 %0, t; }" : "=r"(a) : "l"(p));
    return a;
}
#define CP_ASYNC16(dst, src) \
    asm volatile("cp.async.cg.shared.global [%0], [%1], 16;" :: "r"(dst), "l"(src))
#define CP_COMMIT() asm volatile("cp.async.commit_group;" ::: "memory")
#define CP_WAIT(n)  asm volatile("cp.async.wait_group %0;" :: "n"(n) : "memory")

__device__ __forceinline__ void ldmx4(uint32_t* r, uint32_t addr) {
    asm volatile("ldmatrix.sync.aligned.m8n8.x4.shared.b16 {%0,%1,%2,%3}, [%4];"
        : "=r"(r[0]), "=r"(r[1]), "=r"(r[2]), "=r"(r[3]) : "r"(addr));
}
__device__ __forceinline__ void mma_f16(float* d, const uint32_t* a, const uint32_t* b) {
    asm volatile(
        "mma.sync.aligned.m16n8k16.row.col.f32.f16.f16.f32 "
        "{%0,%1,%2,%3}, {%4,%5,%6,%7}, {%8,%9}, {%0,%1,%2,%3};"
        : "+f"(d[0]), "+f"(d[1]), "+f"(d[2]), "+f"(d[3])
        : "r"(a[0]), "r"(a[1]), "r"(a[2]), "r"(a[3]), "r"(b[0]), "r"(b[1]));
}

// ---------------------------------------------------------------------------
// fp16 mma.sync batched GEMM: C[M,N](f32 or f16) = A[M,K] * B[N,K]^T
//   A, B __half row-major K-contiguous. CTA 128x128, warp tile 32x64.
//   Single __syncthreads per chunk; commit every iter so wait(S-2) pins stage c.
// ---------------------------------------------------------------------------
template<bool CSKIP, bool CKLIM, bool HALF_OUT>
__global__ __launch_bounds__(256, 2)
void h_gemm(const __half* __restrict__ A, const __half* __restrict__ B, void* __restrict__ Cv,
            int M, int N, int K, int lda, int ldb, int ldc,
            long long bA, long long bB, long long bC)
{
    const int row0 = blockIdx.y * BM;
    const int col0 = blockIdx.x * BN;
    if (CSKIP && col0 >= row0 + BM) return;
    const int Keff = CKLIM ? min(K, row0 + BM) : K;
    const int nCh = Keff / BK;

    A += (long long)blockIdx.z * bA;
    B += (long long)blockIdx.z * bB;

    extern __shared__ char smem[];
    const uint32_t sbase = smem_u32(smem);

    const int tid = threadIdx.x;
    const int wid = tid >> 5, lane = tid & 31;
    const int g = lane >> 2, t4 = lane & 3;
    const int warpM = (wid & 3) * 32;             // 4 warp rows x 32
    const int warpN = (wid >> 2) * 64;            // 2 warp cols x 64
    const int lrow = lane & 7, lsel = lane >> 3;

    // per-lane ldmatrix byte offsets within a stage
    const uint32_t aoff = ((warpM + (lsel & 1) * 8 + lrow) * STRIDE + (lsel >> 1) * 8) * 2;
    const uint32_t boff = ((warpN + (lsel >> 1) * 8 + lrow) * STRIDE + (lsel & 1) * 8) * 2;

    float acc[2][8][4];
    #pragma unroll
    for (int i = 0; i < 2; i++)
        #pragma unroll
        for (int j = 0; j < 8; j++)
            #pragma unroll
            for (int q = 0; q < 4; q++) acc[i][j][q] = 0.0f;

    // loader: A,B tiles each 128 rows x 64 halfs = 1024 x 16B units, 4/thread
    auto load_stage = [&](int st, int ch) {
        const uint32_t sA = sbase + st * STAGE_BYTES;
        const uint32_t sB = sA + BM * STRIDE * 2;
        const int k0 = ch * BK;
        #pragma unroll
        for (int i = 0; i < 4; i++) {
            int u = tid + i * 256;
            int r = u >> 3, cu = u & 7;
            CP_ASYNC16(sA + (r * STRIDE + cu * 8) * 2,
                       &A[(size_t)(row0 + r) * lda + k0 + cu * 8]);
        }
        #pragma unroll
        for (int i = 0; i < 4; i++) {
            int u = tid + i * 256;
            int r = u >> 3, cu = u & 7;
            CP_ASYNC16(sB + (r * STRIDE + cu * 8) * 2,
                       &B[(size_t)(col0 + r) * ldb + k0 + cu * 8]);
        }
    };

    // prologue: stages 0..STAGES-2
    #pragma unroll
    for (int p = 0; p < STAGES - 1; ++p) {
        if (p < nCh) load_stage(p, p);
        CP_COMMIT();
    }

    for (int c = 0; c < nCh; ++c) {
        CP_WAIT(STAGES - 2);          // stage c resident
        __syncthreads();              // all warps done with stage (c-1) -> safe to overwrite
        if (c + STAGES - 1 < nCh) load_stage((c + STAGES - 1) % STAGES, c + STAGES - 1);
        CP_COMMIT();                  // unconditional: keeps group accounting exact

        const uint32_t sA = sbase + (c % STAGES) * STAGE_BYTES;
        const uint32_t sB = sA + BM * STRIDE * 2;

        #pragma unroll
        for (int kk = 0; kk < 4; ++kk) {          // four k16 steps per chunk
            uint32_t a[2][4];
            ldmx4(a[0], sA + aoff + kk * 32);
            ldmx4(a[1], sA + aoff + 16 * STRIDE * 2 + kk * 32);
            uint32_t b[8][2];
            #pragma unroll
            for (int j = 0; j < 4; ++j) {
                uint32_t r[4];
                ldmx4(r, sB + boff + j * 16 * STRIDE * 2 + kk * 32);
                b[2 * j][0] = r[0]; b[2 * j][1] = r[1];
                b[2 * j + 1][0] = r[2]; b[2 * j + 1][1] = r[3];
            }
            #pragma unroll
            for (int nt = 0; nt < 8; ++nt) {
                mma_f16(acc[0][nt], a[0], b[nt]);
                mma_f16(acc[1][nt], a[1], b[nt]);
            }
        }
    }

    // epilogue
    #pragma unroll
    for (int mt = 0; mt < 2; mt++) {
        const int r0 = row0 + warpM + mt * 16 + g;
        #pragma unroll
        for (int nt = 0; nt < 8; nt++) {
            const int cc = col0 + warpN + nt * 8 + t4 * 2;
            if (HALF_OUT) {
                __half* C = (__half*)Cv + (long long)blockIdx.z * bC;
                *(__half2*)&C[(size_t)r0 * ldc + cc] =
                    __floats2half2_rn(acc[mt][nt][0], acc[mt][nt][1]);
                *(__half2*)&C[(size_t)(r0 + 8) * ldc + cc] =
                    __floats2half2_rn(acc[mt][nt][2], acc[mt][nt][3]);
            } else {
                float* C = (float*)Cv + (long long)blockIdx.z * bC;
                *(float2*)&C[(size_t)r0 * ldc + cc]       = make_float2(acc[mt][nt][0], acc[mt][nt][1]);
                *(float2*)&C[(size_t)(r0 + 8) * ldc + cc] = make_float2(acc[mt][nt][2], acc[mt][nt][3]);
            }
        }
    }
}

// ---------------------------------------------------------------------------
// Elementwise fp32 -> fp16 convert
// ---------------------------------------------------------------------------
__global__ __launch_bounds__(256)
void convert_h_kernel(const float* __restrict__ in, __half* __restrict__ out, int n)
{
    int i = (blockIdx.x * 256 + threadIdx.x) * 4;
    if (i < n) {
        float4 v = *(const float4*)&in[i];
        __half2 a = __floats2half2_rn(v.x, v.y);
        __half2 b = __floats2half2_rn(v.z, v.w);
        *(__half2*)&out[i]     = a;
        *(__half2*)&out[i + 2] = b;
    }
}

// ---------------------------------------------------------------------------
// Tiled transpose with type conversion: out[C,R] = (Tout)in[R,C]^T
// ---------------------------------------------------------------------------
template<typename Tin, typename Tout>
__global__ __launch_bounds__(256)
void transpose_kernel(const Tin* __restrict__ in, Tout* __restrict__ out, int R, int C)
{
    __shared__ float tile[32][33];
    const int c0 = blockIdx.x * 32, r0 = blockIdx.y * 32;
    const int x = threadIdx.x, y = threadIdx.y;    // block (32, 8)
    #pragma unroll
    for (int i = 0; i < 32; i += 8)
        tile[y + i][x] = (float)in[(size_t)(r0 + y + i) * C + c0 + x];
    __syncthreads();
    #pragma unroll
    for (int i = 0; i < 32; i += 8)
        out[(size_t)(c0 + y + i) * R + r0 + x] = (Tout)tile[x][y + i];
}

// ---------------------------------------------------------------------------
// Fused RMSNorm + NeoX RoPE -> fp16 q/k/v
// ---------------------------------------------------------------------------
__global__ __launch_bounds__(256)
void normrope_kernel(const float* __restrict__ qkv,
                     const int*   __restrict__ positions,
                     const float* __restrict__ qw,
                     const float* __restrict__ kw,
                     __half* __restrict__ q_out,
                     __half* __restrict__ k_out,
                     __half* __restrict__ v_out)
{
    const int h = blockIdx.x;
    const int t = blockIdx.y;
    const int d = threadIdx.x;

    __shared__ float red[256];
    __shared__ float xn[256];

    const int pos = positions[t];
    const size_t row = (size_t)t * QKV_N;
    const size_t out_idx = (size_t)t * (NH * DH) + (size_t)h * DH + d;

    const int fi = d & 127;
    const float inv_freq = expf(-(float)fi * (LN_THETA / 128.0f));
    const float ang = (float)pos * inv_freq;
    const float c = cosf(ang);
    const float s = sinf(ang);

    #pragma unroll
    for (int sec = 0; sec < 3; sec++) {
        const int base = sec * Q_SIZE + h * DH;
        const float x = qkv[row + base + d];

        red[d] = x * x;
        __syncthreads();
        #pragma unroll
        for (int st = 128; st > 0; st >>= 1) {
            if (d < st) red[d] += red[d + st];
            __syncthreads();
        }
        const float rs = rsqrtf(red[0] / (float)DH + EPS);
        __syncthreads();

        float w = 1.0f;
        if (sec == 0) w = qw[d];
        else if (sec == 1) w = kw[d];
        float val = x * rs * w;

        if (sec < 2) {
            xn[d] = val;
            __syncthreads();
            float outv;
            if (d < 128) outv = xn[d] * c - xn[d + 128] * s;
            else         outv = xn[d] * c + xn[d - 128] * s;
            __syncthreads();
            if (sec == 0) q_out[out_idx] = __float2half(outv);
            else          k_out[out_idx] = __float2half(outv);
        } else {
            v_out[out_idx] = __float2half(val);
        }
    }
}

// ---------------------------------------------------------------------------
// Causal softmax: read fp32 scores, write fp16 probs (zero tail to block end)
// ---------------------------------------------------------------------------
__global__ __launch_bounds__(256)
void softmax_kernel(const float* __restrict__ S, __half* __restrict__ P)
{
    const int t = blockIdx.x;
    const int h = blockIdx.y;
    const float* row = S + ((size_t)h * T_SEQ + t) * T_SEQ;
    __half* prow = P + ((size_t)h * T_SEQ + t) * T_SEQ;
    const int L = t + 1;
    const int Lpad = ((t >> 7) + 1) << 7;     // round up to 128 (PV reads this far)
    const int tid = threadIdx.x;
    __shared__ float red[256];

    float m = -FLT_MAX;
    for (int s = tid; s < L; s += 256) m = fmaxf(m, row[s]);
    red[tid] = m;
    __syncthreads();
    #pragma unroll
    for (int st = 128; st > 0; st >>= 1) {
        if (tid < st) red[tid] = fmaxf(red[tid], red[tid + st]);
        __syncthreads();
    }
    m = red[0];
    __syncthreads();

    float sum = 0.0f;
    for (int s = tid; s < L; s += 256) sum += expf(row[s] - m);
    red[tid] = sum;
    __syncthreads();
    #pragma unroll
    for (int st = 128; st > 0; st >>= 1) {
        if (tid < st) red[tid] += red[tid + st];
        __syncthreads();
    }
    const float inv = 1.0f / red[0];
    __syncthreads();

    for (int s = tid; s < Lpad; s += 256)
        prow[s] = (s < L) ? __float2half(expf(row[s] - m) * inv) : __half(0.0f);
}

// ---------------------------------------------------------------------------
// Launch
// ---------------------------------------------------------------------------
extern "C" void kernel_launch(void* const* d_in, const int* in_sizes, int n_in,
                              void* d_out, int out_size)
{
    const float* hidden    = (const float*)d_in[0];
    const int*   positions = (const int*)  d_in[1];
    const float* w_qkv     = (const float*)d_in[2];
    const float* w_o       = (const float*)d_in[3];
    const float* qw        = (const float*)d_in[4];
    const float* kw        = (const float*)d_in[5];
    float* out = (float*)d_out;

    __half *hid_h, *wqkv_h, *wo_h, *qh, *kh, *vh, *vth, *probs, *attn_h;
    float *qkv, *sc;
    cudaGetSymbolAddress((void**)&hid_h,  g_hidden_h);
    cudaGetSymbolAddress((void**)&wqkv_h, g_wqkv_h);
    cudaGetSymbolAddress((void**)&wo_h,   g_wo_h);
    cudaGetSymbolAddress((void**)&qkv,    g_qkv);
    cudaGetSymbolAddress((void**)&qh,     g_qh);
    cudaGetSymbolAddress((void**)&kh,     g_kh);
    cudaGetSymbolAddress((void**)&vh,     g_vh);
    cudaGetSymbolAddress((void**)&vth,    g_vth);
    cudaGetSymbolAddress((void**)&sc,     g_scores);
    cudaGetSymbolAddress((void**)&probs,  g_probs);
    cudaGetSymbolAddress((void**)&attn_h, g_attn_h);

    cudaFuncSetAttribute(h_gemm<false, false, false>, cudaFuncAttributeMaxDynamicSharedMemorySize, SMEM_BYTES);
    cudaFuncSetAttribute(h_gemm<true,  false, false>, cudaFuncAttributeMaxDynamicSharedMemorySize, SMEM_BYTES);
    cudaFuncSetAttribute(h_gemm<false, true,  true >, cudaFuncAttributeMaxDynamicSharedMemorySize, SMEM_BYTES);

    // 0) operand conversions / transposes
    convert_h_kernel<<<(T_SEQ * HID / 4 + 255) / 256, 256>>>(hidden, hid_h, T_SEQ * HID);
    transpose_kernel<float, __half><<<dim3(QKV_N / 32, HID / 32), dim3(32, 8)>>>(w_qkv, wqkv_h, HID, QKV_N);
    transpose_kernel<float, __half><<<dim3(HID / 32,   HID / 32), dim3(32, 8)>>>(w_o,   wo_h,   HID, HID);

    // 1) qkv = hidden @ w_qkv  (fp32 out for exact rmsnorm)
    h_gemm<false, false, false><<<dim3(QKV_N / BN, T_SEQ / BM, 1), 256, SMEM_BYTES>>>(
        hid_h, wqkv_h, qkv, T_SEQ, QKV_N, HID, HID, HID, QKV_N, 0, 0, 0);

    // 2) rmsnorm + rope -> fp16 q/k/v
    normrope_kernel<<<dim3(NH, T_SEQ), 256>>>(qkv, positions, qw, kw, qh, kh, vh);

    // 2b) transpose V -> [NH*DH, T] fp16
    transpose_kernel<__half, __half><<<dim3((NH * DH) / 32, T_SEQ / 32), dim3(32, 8)>>>(vh, vth, T_SEQ, NH * DH);

    // 3) scores[h] = Q_h @ K_h^T (fp32 out, causal tile skip)
    h_gemm<true, false, false><<<dim3(T_SEQ / BN, T_SEQ / BM, NH), 256, SMEM_BYTES>>>(
        qh, kh, sc, T_SEQ, T_SEQ, DH,
        NH * DH, NH * DH, T_SEQ,
        DH, DH, (long long)T_SEQ * T_SEQ);

    // 4) causal softmax -> fp16 probs
    softmax_kernel<<<dim3(T_SEQ, NH), 256>>>(sc, probs);

    // 5) attn[h] = P_h @ V_h (fp16 out, causal K limit)
    h_gemm<false, true, true><<<dim3(DH / BN, T_SEQ / BM, NH), 256, SMEM_BYTES>>>(
        probs, vth, attn_h, T_SEQ, DH, T_SEQ,
        T_SEQ, T_SEQ, NH * DH,
        (long long)T_SEQ * T_SEQ, (long long)DH * T_SEQ, DH);

    // 6) out = attn @ w_o (fp32 out)
    h_gemm<false, false, false><<<dim3(HID / BN, T_SEQ / BM, 1), 256, SMEM_BYTES>>>(
        attn_h, wo_h, out, T_SEQ, HID, Q_SIZE, Q_SIZE, Q_SIZE, HID, 0, 0, 0);

    (void)in_sizes; (void)n_in; (void)out_size;
}

// round 7
// speedup vs baseline: 1.4017x; 1.0992x over previous
#include <cuda_runtime.h>
#include <cuda_fp16.h>
#include <math.h>
#include <float.h>
#include <cstdint>

// Problem constants
#define T_SEQ 2048
#define HID   4096
#define NH    16
#define DH    256
#define QKV_N (3 * NH * DH)      // 12288
#define Q_SIZE (NH * DH)         // 4096
#define EPS   1e-6f
#define LN_THETA 9.210340371976184f   // ln(10000)

// GEMM tile config (fp16 engine): CTA 128x128, warp 32x64, 8 warps, BK=64
#define BM 128
#define BN 128
#define BK 64
#define STRIDE 72
#define STAGES 3
#define STAGE_BYTES ((BM + BN) * STRIDE * 2)   // 36864
#define SMEM_BYTES (STAGES * STAGE_BYTES)      // 110592

// Flash attention config: q-tile 64, kv-tile 64, 4 warps, d split in 2
#define FQ 64
#define QSTR 264                   // 256 + 8 pad (halfs)
#define VSTR 72                    // 64 + 8 pad
#define PSTR 72
#define OFF_K (FQ * QSTR * 2)                  // 33792
#define OFF_V (2 * FQ * QSTR * 2)              // 67584
#define OFF_P (OFF_V + 128 * VSTR * 2)         // 86016
#define FLASH_SMEM (OFF_P + FQ * PSTR * 2)     // 95232

// ---------------------------------------------------------------------------
// Scratch (static device globals)
// ---------------------------------------------------------------------------
__device__ __half g_hidden_h[(size_t)T_SEQ * HID];
__device__ __half g_wqkv_h[(size_t)QKV_N * HID];
__device__ __half g_wo_h[(size_t)HID * Q_SIZE];
__device__ float  g_qkv[(size_t)T_SEQ * QKV_N];
__device__ __half g_qh[(size_t)T_SEQ * NH * DH];
__device__ __half g_kh[(size_t)T_SEQ * NH * DH];
__device__ __half g_vh[(size_t)T_SEQ * NH * DH];
__device__ __half g_vth[(size_t)NH * DH * T_SEQ];
__device__ __half g_attn_h[(size_t)T_SEQ * NH * DH];

// ---------------------------------------------------------------------------
// PTX helpers
// ---------------------------------------------------------------------------
__device__ __forceinline__ uint32_t smem_u32(const void* p) {
    uint32_t a;
    asm("{ .reg .u64 t; cvta.to.shared.u64 t, %1; cvt.u32.u64 %0, t; }" : "=r"(a) : "l"(p));
    return a;
}
#define CP_ASYNC16(dst, src) \
    asm volatile("cp.async.cg.shared.global [%0], [%1], 16;" :: "r"(dst), "l"(src))
#define CP_COMMIT() asm volatile("cp.async.commit_group;" ::: "memory")
#define CP_WAIT(n)  asm volatile("cp.async.wait_group %0;" :: "n"(n) : "memory")

__device__ __forceinline__ void ldmx4(uint32_t* r, uint32_t addr) {
    asm volatile("ldmatrix.sync.aligned.m8n8.x4.shared.b16 {%0,%1,%2,%3}, [%4];"
        : "=r"(r[0]), "=r"(r[1]), "=r"(r[2]), "=r"(r[3]) : "r"(addr));
}
__device__ __forceinline__ void mma_f16(float* d, const uint32_t* a, const uint32_t* b) {
    asm volatile(
        "mma.sync.aligned.m16n8k16.row.col.f32.f16.f16.f32 "
        "{%0,%1,%2,%3}, {%4,%5,%6,%7}, {%8,%9}, {%0,%1,%2,%3};"
        : "+f"(d[0]), "+f"(d[1]), "+f"(d[2]), "+f"(d[3])
        : "r"(a[0]), "r"(a[1]), "r"(a[2]), "r"(a[3]), "r"(b[0]), "r"(b[1]));
}

// ---------------------------------------------------------------------------
// fp16 mma.sync GEMM: C[M,N] = A[M,K] * B[N,K]^T (unchanged from R6)
// ---------------------------------------------------------------------------
template<bool CSKIP, bool CKLIM, bool HALF_OUT>
__global__ __launch_bounds__(256, 2)
void h_gemm(const __half* __restrict__ A, const __half* __restrict__ B, void* __restrict__ Cv,
            int M, int N, int K, int lda, int ldb, int ldc,
            long long bA, long long bB, long long bC)
{
    const int row0 = blockIdx.y * BM;
    const int col0 = blockIdx.x * BN;
    if (CSKIP && col0 >= row0 + BM) return;
    const int Keff = CKLIM ? min(K, row0 + BM) : K;
    const int nCh = Keff / BK;

    A += (long long)blockIdx.z * bA;
    B += (long long)blockIdx.z * bB;

    extern __shared__ char smem[];
    const uint32_t sbase = smem_u32(smem);

    const int tid = threadIdx.x;
    const int wid = tid >> 5, lane = tid & 31;
    const int g = lane >> 2, t4 = lane & 3;
    const int warpM = (wid & 3) * 32;
    const int warpN = (wid >> 2) * 64;
    const int lrow = lane & 7, lsel = lane >> 3;

    const uint32_t aoff = ((warpM + (lsel & 1) * 8 + lrow) * STRIDE + (lsel >> 1) * 8) * 2;
    const uint32_t boff = ((warpN + (lsel >> 1) * 8 + lrow) * STRIDE + (lsel & 1) * 8) * 2;

    float acc[2][8][4];
    #pragma unroll
    for (int i = 0; i < 2; i++)
        #pragma unroll
        for (int j = 0; j < 8; j++)
            #pragma unroll
            for (int q = 0; q < 4; q++) acc[i][j][q] = 0.0f;

    auto load_stage = [&](int st, int ch) {
        const uint32_t sA = sbase + st * STAGE_BYTES;
        const uint32_t sB = sA + BM * STRIDE * 2;
        const int k0 = ch * BK;
        #pragma unroll
        for (int i = 0; i < 4; i++) {
            int u = tid + i * 256;
            int r = u >> 3, cu = u & 7;
            CP_ASYNC16(sA + (r * STRIDE + cu * 8) * 2,
                       &A[(size_t)(row0 + r) * lda + k0 + cu * 8]);
        }
        #pragma unroll
        for (int i = 0; i < 4; i++) {
            int u = tid + i * 256;
            int r = u >> 3, cu = u & 7;
            CP_ASYNC16(sB + (r * STRIDE + cu * 8) * 2,
                       &B[(size_t)(col0 + r) * ldb + k0 + cu * 8]);
        }
    };

    #pragma unroll
    for (int p = 0; p < STAGES - 1; ++p) {
        if (p < nCh) load_stage(p, p);
        CP_COMMIT();
    }

    for (int c = 0; c < nCh; ++c) {
        CP_WAIT(STAGES - 2);
        __syncthreads();
        if (c + STAGES - 1 < nCh) load_stage((c + STAGES - 1) % STAGES, c + STAGES - 1);
        CP_COMMIT();

        const uint32_t sA = sbase + (c % STAGES) * STAGE_BYTES;
        const uint32_t sB = sA + BM * STRIDE * 2;

        #pragma unroll
        for (int kk = 0; kk < 4; ++kk) {
            uint32_t a[2][4];
            ldmx4(a[0], sA + aoff + kk * 32);
            ldmx4(a[1], sA + aoff + 16 * STRIDE * 2 + kk * 32);
            uint32_t b[8][2];
            #pragma unroll
            for (int j = 0; j < 4; ++j) {
                uint32_t r[4];
                ldmx4(r, sB + boff + j * 16 * STRIDE * 2 + kk * 32);
                b[2 * j][0] = r[0]; b[2 * j][1] = r[1];
                b[2 * j + 1][0] = r[2]; b[2 * j + 1][1] = r[3];
            }
            #pragma unroll
            for (int nt = 0; nt < 8; ++nt) {
                mma_f16(acc[0][nt], a[0], b[nt]);
                mma_f16(acc[1][nt], a[1], b[nt]);
            }
        }
    }

    #pragma unroll
    for (int mt = 0; mt < 2; mt++) {
        const int r0 = row0 + warpM + mt * 16 + g;
        #pragma unroll
        for (int nt = 0; nt < 8; nt++) {
            const int cc = col0 + warpN + nt * 8 + t4 * 2;
            if (HALF_OUT) {
                __half* C = (__half*)Cv + (long long)blockIdx.z * bC;
                *(__half2*)&C[(size_t)r0 * ldc + cc] =
                    __floats2half2_rn(acc[mt][nt][0], acc[mt][nt][1]);
                *(__half2*)&C[(size_t)(r0 + 8) * ldc + cc] =
                    __floats2half2_rn(acc[mt][nt][2], acc[mt][nt][3]);
            } else {
                float* C = (float*)Cv + (long long)blockIdx.z * bC;
                *(float2*)&C[(size_t)r0 * ldc + cc]       = make_float2(acc[mt][nt][0], acc[mt][nt][1]);
                *(float2*)&C[(size_t)(r0 + 8) * ldc + cc] = make_float2(acc[mt][nt][2], acc[mt][nt][3]);
            }
        }
    }
}

// ---------------------------------------------------------------------------
// Fused flash attention: per CTA = (64 q rows, head, d-half)
//   Q [T, NH*DH] fp16, K same, Vt [NH*DH, T] fp16 -> O [T, NH*DH] fp16
// ---------------------------------------------------------------------------
__global__ __launch_bounds__(128, 2)
void flash_kernel(const __half* __restrict__ Qg, const __half* __restrict__ Kg,
                  const __half* __restrict__ Vt, __half* __restrict__ Og)
{
    const int qtile = gridDim.x - 1 - blockIdx.x;   // longest work first
    const int q0 = qtile * FQ;
    const int h  = blockIdx.y;
    const int dh = blockIdx.z;

    extern __shared__ char sm[];
    const uint32_t sb = smem_u32(sm);
    const uint32_t Qs = sb, Ks = sb + OFF_K, Vs = sb + OFF_V, Ps = sb + OFF_P;

    const int tid = threadIdx.x;
    const int w = tid >> 5, lane = tid & 31;
    const int g = lane >> 2, t4 = lane & 3;
    const int lrow = lane & 7, lsel = lane >> 3;

    const __half* Qp = Qg + (size_t)h * DH;
    const __half* Kp = Kg + (size_t)h * DH;
    const __half* Vp = Vt + (size_t)(h * DH + dh * 128) * T_SEQ;

    // load Q tile (64 x 256)
    #pragma unroll
    for (int i = 0; i < 16; i++) {
        int u = tid + i * 128;
        int r = u >> 5, cu = u & 31;
        CP_ASYNC16(Qs + (r * QSTR + cu * 8) * 2, Qp + (size_t)(q0 + r) * Q_SIZE + cu * 8);
    }
    CP_COMMIT();

    const uint32_t aoffQ = ((w * 16 + (lsel & 1) * 8 + lrow) * QSTR + (lsel >> 1) * 8) * 2;
    const uint32_t boffK = (((lsel >> 1) * 8 + lrow) * QSTR + (lsel & 1) * 8) * 2;
    const uint32_t aoffP = ((w * 16 + (lsel & 1) * 8 + lrow) * PSTR + (lsel >> 1) * 8) * 2;
    const uint32_t boffV = (((lsel >> 1) * 8 + lrow) * VSTR + (lsel & 1) * 8) * 2;

    float m0 = -1e30f, m1 = -1e30f, l0 = 0.0f, l1 = 0.0f;
    float o[16][4];
    #pragma unroll
    for (int i = 0; i < 16; i++)
        #pragma unroll
        for (int q = 0; q < 4; q++) o[i][q] = 0.0f;

    const int nkv = qtile + 1;
    for (int it = 0; it < nkv; ++it) {
        const int kv0 = it * FQ;
        __syncthreads();                       // all warps done reading K/V of prev tile
        #pragma unroll
        for (int i = 0; i < 16; i++) {
            int u = tid + i * 128;
            int r = u >> 5, cu = u & 31;
            CP_ASYNC16(Ks + (r * QSTR + cu * 8) * 2, Kp + (size_t)(kv0 + r) * Q_SIZE + cu * 8);
        }
        #pragma unroll
        for (int i = 0; i < 8; i++) {
            int u = tid + i * 128;
            int r = u >> 3, cu = u & 7;
            CP_ASYNC16(Vs + (r * VSTR + cu * 8) * 2, Vp + (size_t)r * T_SEQ + kv0 + cu * 8);
        }
        CP_COMMIT();
        CP_WAIT(0);
        __syncthreads();

        // S = Q K^T  (16 q rows per warp x 64 kv cols)
        float s[8][4];
        #pragma unroll
        for (int i = 0; i < 8; i++)
            #pragma unroll
            for (int q = 0; q < 4; q++) s[i][q] = 0.0f;
        #pragma unroll
        for (int ks = 0; ks < 16; ++ks) {
            uint32_t a[4];
            ldmx4(a, Qs + aoffQ + ks * 32);
            #pragma unroll
            for (int j = 0; j < 4; ++j) {
                uint32_t r4[4];
                ldmx4(r4, Ks + boffK + j * 16 * QSTR * 2 + ks * 32);
                mma_f16(s[2 * j], a, r4);
                mma_f16(s[2 * j + 1], a, r4 + 2);
            }
        }

        // causal mask (only on the diagonal tile)
        if (kv0 == q0) {
            const int rowg = w * 16 + g;
            #pragma unroll
            for (int nt = 0; nt < 8; ++nt) {
                const int col = nt * 8 + t4 * 2;
                if (col     > rowg)     s[nt][0] = -1e30f;
                if (col + 1 > rowg)     s[nt][1] = -1e30f;
                if (col     > rowg + 8) s[nt][2] = -1e30f;
                if (col + 1 > rowg + 8) s[nt][3] = -1e30f;
            }
        }

        // online softmax, rows g (r=0) and g+8 (r=1)
        #pragma unroll
        for (int r = 0; r < 2; ++r) {
            float mx = -1e30f;
            #pragma unroll
            for (int nt = 0; nt < 8; ++nt)
                mx = fmaxf(mx, fmaxf(s[nt][2 * r], s[nt][2 * r + 1]));
            mx = fmaxf(mx, __shfl_xor_sync(0xffffffffu, mx, 1));
            mx = fmaxf(mx, __shfl_xor_sync(0xffffffffu, mx, 2));
            const float mold = r ? m1 : m0;
            const float mnew = fmaxf(mold, mx);
            const float sc = __expf(mold - mnew);
            float sum = 0.0f;
            #pragma unroll
            for (int nt = 0; nt < 8; ++nt) {
                float p0 = __expf(s[nt][2 * r] - mnew);
                float p1 = __expf(s[nt][2 * r + 1] - mnew);
                s[nt][2 * r] = p0; s[nt][2 * r + 1] = p1;
                sum += p0 + p1;
            }
            sum += __shfl_xor_sync(0xffffffffu, sum, 1);
            sum += __shfl_xor_sync(0xffffffffu, sum, 2);
            if (r == 0) { l0 = l0 * sc + sum; m0 = mnew; }
            else        { l1 = l1 * sc + sum; m1 = mnew; }
            #pragma unroll
            for (int nt = 0; nt < 16; ++nt) {
                o[nt][2 * r]     *= sc;
                o[nt][2 * r + 1] *= sc;
            }
        }

        // P -> per-warp smem slice (rows w*16..w*16+15)
        #pragma unroll
        for (int nt = 0; nt < 8; ++nt) {
            *(__half2*)(sm + OFF_P + ((w * 16 + g)     * PSTR + nt * 8 + t4 * 2) * 2) =
                __floats2half2_rn(s[nt][0], s[nt][1]);
            *(__half2*)(sm + OFF_P + ((w * 16 + g + 8) * PSTR + nt * 8 + t4 * 2) * 2) =
                __floats2half2_rn(s[nt][2], s[nt][3]);
        }
        __syncwarp();

        // O += P V  (k = 64 kv, n = 128 d cols)
        #pragma unroll
        for (int ks2 = 0; ks2 < 4; ++ks2) {
            uint32_t a[4];
            ldmx4(a, Ps + aoffP + ks2 * 32);
            #pragma unroll
            for (int j = 0; j < 8; ++j) {
                uint32_t r4[4];
                ldmx4(r4, Vs + boffV + j * 16 * VSTR * 2 + ks2 * 32);
                mma_f16(o[2 * j], a, r4);
                mma_f16(o[2 * j + 1], a, r4 + 2);
            }
        }
        __syncwarp();
    }

    // write O / l
    const float i0 = 1.0f / l0, i1 = 1.0f / l1;
    const int tg = q0 + w * 16 + g;
    #pragma unroll
    for (int nt = 0; nt < 16; ++nt) {
        const int col = h * DH + dh * 128 + nt * 8 + t4 * 2;
        *(__half2*)&Og[(size_t)tg * Q_SIZE + col] =
            __floats2half2_rn(o[nt][0] * i0, o[nt][1] * i0);
        *(__half2*)&Og[(size_t)(tg + 8) * Q_SIZE + col] =
            __floats2half2_rn(o[nt][2] * i1, o[nt][3] * i1);
    }
}

// ---------------------------------------------------------------------------
// Elementwise fp32 -> fp16 convert
// ---------------------------------------------------------------------------
__global__ __launch_bounds__(256)
void convert_h_kernel(const float* __restrict__ in, __half* __restrict__ out, int n)
{
    int i = (blockIdx.x * 256 + threadIdx.x) * 4;
    if (i < n) {
        float4 v = *(const float4*)&in[i];
        *(__half2*)&out[i]     = __floats2half2_rn(v.x, v.y);
        *(__half2*)&out[i + 2] = __floats2half2_rn(v.z, v.w);
    }
}

// ---------------------------------------------------------------------------
// Tiled transpose with type conversion
// ---------------------------------------------------------------------------
template<typename Tin, typename Tout>
__global__ __launch_bounds__(256)
void transpose_kernel(const Tin* __restrict__ in, Tout* __restrict__ out, int R, int C)
{
    __shared__ float tile[32][33];
    const int c0 = blockIdx.x * 32, r0 = blockIdx.y * 32;
    const int x = threadIdx.x, y = threadIdx.y;
    #pragma unroll
    for (int i = 0; i < 32; i += 8)
        tile[y + i][x] = (float)in[(size_t)(r0 + y + i) * C + c0 + x];
    __syncthreads();
    #pragma unroll
    for (int i = 0; i < 32; i += 8)
        out[(size_t)(c0 + y + i) * R + r0 + x] = (Tout)tile[x][y + i];
}

// ---------------------------------------------------------------------------
// Fused RMSNorm + NeoX RoPE, warp-per-(t,h): pairs (d, d+128) in-thread
// ---------------------------------------------------------------------------
__global__ __launch_bounds__(128)
void normrope_kernel(const float* __restrict__ qkv,
                     const int*   __restrict__ positions,
                     const float* __restrict__ qw,
                     const float* __restrict__ kw,
                     __half* __restrict__ q_out,
                     __half* __restrict__ k_out,
                     __half* __restrict__ v_out)
{
    const int wg = blockIdx.x * 4 + (threadIdx.x >> 5);
    const int t = wg >> 4, h = wg & 15;
    const int lane = threadIdx.x & 31;
    const int pos = positions[t];
    const size_t row = (size_t)t * QKV_N;
    const size_t obase = (size_t)t * Q_SIZE + h * DH;

    float c[4], sn[4];
    #pragma unroll
    for (int i = 0; i < 4; i++) {
        const float fi = (float)(lane + 32 * i);
        const float fr = expf(-fi * (LN_THETA / 128.0f));
        sincosf((float)pos * fr, &sn[i], &c[i]);
    }

    #pragma unroll
    for (int sec = 0; sec < 3; sec++) {
        const size_t base = row + sec * Q_SIZE + h * DH;
        float x[8];
        #pragma unroll
        for (int i = 0; i < 8; i++) x[i] = qkv[base + lane + 32 * i];
        float ss = 0.0f;
        #pragma unroll
        for (int i = 0; i < 8; i++) ss += x[i] * x[i];
        #pragma unroll
        for (int off = 16; off > 0; off >>= 1) ss += __shfl_xor_sync(0xffffffffu, ss, off);
        const float rs = rsqrtf(ss * (1.0f / DH) + EPS);

        float v[8];
        #pragma unroll
        for (int i = 0; i < 8; i++) {
            float w = 1.0f;
            if (sec == 0) w = qw[lane + 32 * i];
            else if (sec == 1) w = kw[lane + 32 * i];
            v[i] = x[i] * rs * w;
        }
        if (sec < 2) {
            __half* outp = sec == 0 ? q_out : k_out;
            #pragma unroll
            for (int i = 0; i < 4; i++) {
                outp[obase + lane + 32 * i]       = __float2half(v[i] * c[i] - v[i + 4] * sn[i]);
                outp[obase + lane + 32 * i + 128] = __float2half(v[i + 4] * c[i] + v[i] * sn[i]);
            }
        } else {
            #pragma unroll
            for (int i = 0; i < 8; i++)
                v_out[obase + lane + 32 * i] = __float2half(v[i]);
        }
    }
}

// ---------------------------------------------------------------------------
// Launch
// ---------------------------------------------------------------------------
extern "C" void kernel_launch(void* const* d_in, const int* in_sizes, int n_in,
                              void* d_out, int out_size)
{
    const float* hidden    = (const float*)d_in[0];
    const int*   positions = (const int*)  d_in[1];
    const float* w_qkv     = (const float*)d_in[2];
    const float* w_o       = (const float*)d_in[3];
    const float* qw        = (const float*)d_in[4];
    const float* kw        = (const float*)d_in[5];
    float* out = (float*)d_out;

    __half *hid_h, *wqkv_h, *wo_h, *qh, *kh, *vh, *vth, *attn_h;
    float *qkv;
    cudaGetSymbolAddress((void**)&hid_h,  g_hidden_h);
    cudaGetSymbolAddress((void**)&wqkv_h, g_wqkv_h);
    cudaGetSymbolAddress((void**)&wo_h,   g_wo_h);
    cudaGetSymbolAddress((void**)&qkv,    g_qkv);
    cudaGetSymbolAddress((void**)&qh,     g_qh);
    cudaGetSymbolAddress((void**)&kh,     g_kh);
    cudaGetSymbolAddress((void**)&vh,     g_vh);
    cudaGetSymbolAddress((void**)&vth,    g_vth);
    cudaGetSymbolAddress((void**)&attn_h, g_attn_h);

    cudaFuncSetAttribute(h_gemm<false, false, false>, cudaFuncAttributeMaxDynamicSharedMemorySize, SMEM_BYTES);
    cudaFuncSetAttribute(flash_kernel, cudaFuncAttributeMaxDynamicSharedMemorySize, FLASH_SMEM);

    // 0) operand conversions / transposes
    convert_h_kernel<<<(T_SEQ * HID / 4 + 255) / 256, 256>>>(hidden, hid_h, T_SEQ * HID);
    transpose_kernel<float, __half><<<dim3(QKV_N / 32, HID / 32), dim3(32, 8)>>>(w_qkv, wqkv_h, HID, QKV_N);
    transpose_kernel<float, __half><<<dim3(HID / 32,   HID / 32), dim3(32, 8)>>>(w_o,   wo_h,   HID, HID);

    // 1) qkv = hidden @ w_qkv  (fp32 out for exact rmsnorm)
    h_gemm<false, false, false><<<dim3(QKV_N / BN, T_SEQ / BM, 1), 256, SMEM_BYTES>>>(
        hid_h, wqkv_h, qkv, T_SEQ, QKV_N, HID, HID, HID, QKV_N, 0, 0, 0);

    // 2) rmsnorm + rope -> fp16 q/k/v  (warp per (t,h))
    normrope_kernel<<<T_SEQ * NH / 4, 128>>>(qkv, positions, qw, kw, qh, kh, vh);

    // 2b) transpose V -> [NH*DH, T] fp16
    transpose_kernel<__half, __half><<<dim3((NH * DH) / 32, T_SEQ / 32), dim3(32, 8)>>>(vh, vth, T_SEQ, NH * DH);

    // 3) fused causal attention -> attn_h fp16
    flash_kernel<<<dim3(T_SEQ / FQ, NH, 2), 128, FLASH_SMEM>>>(qh, kh, vth, attn_h);

    // 4) out = attn @ w_o (fp32 out)
    h_gemm<false, false, false><<<dim3(HID / BN, T_SEQ / BM, 1), 256, SMEM_BYTES>>>(
        attn_h, wo_h, out, T_SEQ, HID, Q_SIZE, Q_SIZE, Q_SIZE, HID, 0, 0, 0);

    (void)in_sizes; (void)n_in; (void)out_size;
}

// round 8
// speedup vs baseline: 1.5387x; 1.0978x over previous
#include <cuda_runtime.h>
#include <cuda_fp16.h>
#include <math.h>
#include <float.h>
#include <cstdint>

// Problem constants
#define T_SEQ 2048
#define HID   4096
#define NH    16
#define DH    256
#define QKV_N (3 * NH * DH)      // 12288
#define Q_SIZE (NH * DH)         // 4096
#define EPS   1e-6f
#define LN_THETA 9.210340371976184f   // ln(10000)

// GEMM tile config (fp16 engine): CTA 128x128, warp 32x64, 8 warps, BK=64
#define BM 128
#define BN 128
#define BK 64
#define STRIDE 72
#define STAGES 3
#define STAGE_BYTES ((BM + BN) * STRIDE * 2)   // 36864
#define SMEM_BYTES (STAGES * STAGE_BYTES)      // 110592

// Flash attention config: q-tile 64, kv-tile 64, 4 warps, d split in 2
#define FQ 64
#define QSTR 264
#define VSTR 72
#define PSTR 72
#define OFF_K (FQ * QSTR * 2)
#define OFF_V (2 * FQ * QSTR * 2)
#define OFF_P (OFF_V + 128 * VSTR * 2)
#define FLASH_SMEM (OFF_P + FQ * PSTR * 2)     // 95232

// ---------------------------------------------------------------------------
// Scratch (static device globals)
// ---------------------------------------------------------------------------
__device__ __half g_hidden_h[(size_t)T_SEQ * HID];
__device__ __half g_wqkv_h[(size_t)QKV_N * HID];
__device__ __half g_wo_h[(size_t)HID * Q_SIZE];
__device__ float  g_qkv[(size_t)T_SEQ * QKV_N];
__device__ __half g_qh[(size_t)T_SEQ * NH * DH];
__device__ __half g_kh[(size_t)T_SEQ * NH * DH];
__device__ __half g_vh[(size_t)T_SEQ * NH * DH];
__device__ __half g_vth[(size_t)NH * DH * T_SEQ];
__device__ __half g_attn_h[(size_t)T_SEQ * NH * DH];

// ---------------------------------------------------------------------------
// PTX helpers
// ---------------------------------------------------------------------------
__device__ __forceinline__ uint32_t smem_u32(const void* p) {
    uint32_t a;
    asm("{ .reg .u64 t; cvta.to.shared.u64 t, %1; cvt.u32.u64 %0, t; }" : "=r"(a) : "l"(p));
    return a;
}
#define CP_ASYNC16(dst, src) \
    asm volatile("cp.async.cg.shared.global [%0], [%1], 16;" :: "r"(dst), "l"(src))
#define CP_COMMIT() asm volatile("cp.async.commit_group;" ::: "memory")
#define CP_WAIT(n)  asm volatile("cp.async.wait_group %0;" :: "n"(n) : "memory")

__device__ __forceinline__ void ldmx4(uint32_t* r, uint32_t addr) {
    asm volatile("ldmatrix.sync.aligned.m8n8.x4.shared.b16 {%0,%1,%2,%3}, [%4];"
        : "=r"(r[0]), "=r"(r[1]), "=r"(r[2]), "=r"(r[3]) : "r"(addr));
}
__device__ __forceinline__ void mma_f16(float* d, const uint32_t* a, const uint32_t* b) {
    asm volatile(
        "mma.sync.aligned.m16n8k16.row.col.f32.f16.f16.f32 "
        "{%0,%1,%2,%3}, {%4,%5,%6,%7}, {%8,%9}, {%0,%1,%2,%3};"
        : "+f"(d[0]), "+f"(d[1]), "+f"(d[2]), "+f"(d[3])
        : "r"(a[0]), "r"(a[1]), "r"(a[2]), "r"(a[3]), "r"(b[0]), "r"(b[1]));
}

// ---------------------------------------------------------------------------
// fp16 mma.sync GEMM: C[M,N] = A[M,K] * B[N,K]^T
//   Chunk reorder: compute k-step 0, then issue next-stage cp.asyncs, then k 1..3.
// ---------------------------------------------------------------------------
template<bool CSKIP, bool CKLIM, bool HALF_OUT>
__global__ __launch_bounds__(256, 2)
void h_gemm(const __half* __restrict__ A, const __half* __restrict__ B, void* __restrict__ Cv,
            int M, int N, int K, int lda, int ldb, int ldc,
            long long bA, long long bB, long long bC)
{
    const int row0 = blockIdx.y * BM;
    const int col0 = blockIdx.x * BN;
    if (CSKIP && col0 >= row0 + BM) return;
    const int Keff = CKLIM ? min(K, row0 + BM) : K;
    const int nCh = Keff / BK;

    A += (long long)blockIdx.z * bA;
    B += (long long)blockIdx.z * bB;

    extern __shared__ char smem[];
    const uint32_t sbase = smem_u32(smem);

    const int tid = threadIdx.x;
    const int wid = tid >> 5, lane = tid & 31;
    const int g = lane >> 2, t4 = lane & 3;
    const int warpM = (wid & 3) * 32;
    const int warpN = (wid >> 2) * 64;
    const int lrow = lane & 7, lsel = lane >> 3;

    const uint32_t aoff = ((warpM + (lsel & 1) * 8 + lrow) * STRIDE + (lsel >> 1) * 8) * 2;
    const uint32_t boff = ((warpN + (lsel >> 1) * 8 + lrow) * STRIDE + (lsel & 1) * 8) * 2;

    float acc[2][8][4];
    #pragma unroll
    for (int i = 0; i < 2; i++)
        #pragma unroll
        for (int j = 0; j < 8; j++)
            #pragma unroll
            for (int q = 0; q < 4; q++) acc[i][j][q] = 0.0f;

    auto load_stage = [&](int st, int ch) {
        const uint32_t sA = sbase + st * STAGE_BYTES;
        const uint32_t sB = sA + BM * STRIDE * 2;
        const int k0 = ch * BK;
        #pragma unroll
        for (int i = 0; i < 4; i++) {
            int u = tid + i * 256;
            int r = u >> 3, cu = u & 7;
            CP_ASYNC16(sA + (r * STRIDE + cu * 8) * 2,
                       &A[(size_t)(row0 + r) * lda + k0 + cu * 8]);
        }
        #pragma unroll
        for (int i = 0; i < 4; i++) {
            int u = tid + i * 256;
            int r = u >> 3, cu = u & 7;
            CP_ASYNC16(sB + (r * STRIDE + cu * 8) * 2,
                       &B[(size_t)(col0 + r) * ldb + k0 + cu * 8]);
        }
    };

    auto compute_k16 = [&](uint32_t sA, uint32_t sB, int kk) {
        uint32_t a[2][4];
        ldmx4(a[0], sA + aoff + kk * 32);
        ldmx4(a[1], sA + aoff + 16 * STRIDE * 2 + kk * 32);
        uint32_t b[8][2];
        #pragma unroll
        for (int j = 0; j < 4; ++j) {
            uint32_t r[4];
            ldmx4(r, sB + boff + j * 16 * STRIDE * 2 + kk * 32);
            b[2 * j][0] = r[0]; b[2 * j][1] = r[1];
            b[2 * j + 1][0] = r[2]; b[2 * j + 1][1] = r[3];
        }
        #pragma unroll
        for (int nt = 0; nt < 8; ++nt) {
            mma_f16(acc[0][nt], a[0], b[nt]);
            mma_f16(acc[1][nt], a[1], b[nt]);
        }
    };

    #pragma unroll
    for (int p = 0; p < STAGES - 1; ++p) {
        if (p < nCh) load_stage(p, p);
        CP_COMMIT();
    }

    for (int c = 0; c < nCh; ++c) {
        CP_WAIT(STAGES - 2);
        __syncthreads();

        const uint32_t sA = sbase + (c % STAGES) * STAGE_BYTES;
        const uint32_t sB = sA + BM * STRIDE * 2;

        compute_k16(sA, sB, 0);                     // start math first
        if (c + STAGES - 1 < nCh) load_stage((c + STAGES - 1) % STAGES, c + STAGES - 1);
        CP_COMMIT();
        #pragma unroll
        for (int kk = 1; kk < 4; ++kk)
            compute_k16(sA, sB, kk);
    }

    #pragma unroll
    for (int mt = 0; mt < 2; mt++) {
        const int r0 = row0 + warpM + mt * 16 + g;
        #pragma unroll
        for (int nt = 0; nt < 8; nt++) {
            const int cc = col0 + warpN + nt * 8 + t4 * 2;
            if (HALF_OUT) {
                __half* C = (__half*)Cv + (long long)blockIdx.z * bC;
                *(__half2*)&C[(size_t)r0 * ldc + cc] =
                    __floats2half2_rn(acc[mt][nt][0], acc[mt][nt][1]);
                *(__half2*)&C[(size_t)(r0 + 8) * ldc + cc] =
                    __floats2half2_rn(acc[mt][nt][2], acc[mt][nt][3]);
            } else {
                float* C = (float*)Cv + (long long)blockIdx.z * bC;
                *(float2*)&C[(size_t)r0 * ldc + cc]       = make_float2(acc[mt][nt][0], acc[mt][nt][1]);
                *(float2*)&C[(size_t)(r0 + 8) * ldc + cc] = make_float2(acc[mt][nt][2], acc[mt][nt][3]);
            }
        }
    }
}

// ---------------------------------------------------------------------------
// Fused flash attention (unchanged from R7)
// ---------------------------------------------------------------------------
__global__ __launch_bounds__(128, 2)
void flash_kernel(const __half* __restrict__ Qg, const __half* __restrict__ Kg,
                  const __half* __restrict__ Vt, __half* __restrict__ Og)
{
    const int qtile = gridDim.x - 1 - blockIdx.x;
    const int q0 = qtile * FQ;
    const int h  = blockIdx.y;
    const int dh = blockIdx.z;

    extern __shared__ char sm[];
    const uint32_t sb = smem_u32(sm);
    const uint32_t Qs = sb, Ks = sb + OFF_K, Vs = sb + OFF_V, Ps = sb + OFF_P;

    const int tid = threadIdx.x;
    const int w = tid >> 5, lane = tid & 31;
    const int g = lane >> 2, t4 = lane & 3;
    const int lrow = lane & 7, lsel = lane >> 3;

    const __half* Qp = Qg + (size_t)h * DH;
    const __half* Kp = Kg + (size_t)h * DH;
    const __half* Vp = Vt + (size_t)(h * DH + dh * 128) * T_SEQ;

    #pragma unroll
    for (int i = 0; i < 16; i++) {
        int u = tid + i * 128;
        int r = u >> 5, cu = u & 31;
        CP_ASYNC16(Qs + (r * QSTR + cu * 8) * 2, Qp + (size_t)(q0 + r) * Q_SIZE + cu * 8);
    }
    CP_COMMIT();

    const uint32_t aoffQ = ((w * 16 + (lsel & 1) * 8 + lrow) * QSTR + (lsel >> 1) * 8) * 2;
    const uint32_t boffK = (((lsel >> 1) * 8 + lrow) * QSTR + (lsel & 1) * 8) * 2;
    const uint32_t aoffP = ((w * 16 + (lsel & 1) * 8 + lrow) * PSTR + (lsel >> 1) * 8) * 2;
    const uint32_t boffV = (((lsel >> 1) * 8 + lrow) * VSTR + (lsel & 1) * 8) * 2;

    float m0 = -1e30f, m1 = -1e30f, l0 = 0.0f, l1 = 0.0f;
    float o[16][4];
    #pragma unroll
    for (int i = 0; i < 16; i++)
        #pragma unroll
        for (int q = 0; q < 4; q++) o[i][q] = 0.0f;

    const int nkv = qtile + 1;
    for (int it = 0; it < nkv; ++it) {
        const int kv0 = it * FQ;
        __syncthreads();
        #pragma unroll
        for (int i = 0; i < 16; i++) {
            int u = tid + i * 128;
            int r = u >> 5, cu = u & 31;
            CP_ASYNC16(Ks + (r * QSTR + cu * 8) * 2, Kp + (size_t)(kv0 + r) * Q_SIZE + cu * 8);
        }
        #pragma unroll
        for (int i = 0; i < 8; i++) {
            int u = tid + i * 128;
            int r = u >> 3, cu = u & 7;
            CP_ASYNC16(Vs + (r * VSTR + cu * 8) * 2, Vp + (size_t)r * T_SEQ + kv0 + cu * 8);
        }
        CP_COMMIT();
        CP_WAIT(0);
        __syncthreads();

        float s[8][4];
        #pragma unroll
        for (int i = 0; i < 8; i++)
            #pragma unroll
            for (int q = 0; q < 4; q++) s[i][q] = 0.0f;
        #pragma unroll
        for (int ks = 0; ks < 16; ++ks) {
            uint32_t a[4];
            ldmx4(a, Qs + aoffQ + ks * 32);
            #pragma unroll
            for (int j = 0; j < 4; ++j) {
                uint32_t r4[4];
                ldmx4(r4, Ks + boffK + j * 16 * QSTR * 2 + ks * 32);
                mma_f16(s[2 * j], a, r4);
                mma_f16(s[2 * j + 1], a, r4 + 2);
            }
        }

        if (kv0 == q0) {
            const int rowg = w * 16 + g;
            #pragma unroll
            for (int nt = 0; nt < 8; ++nt) {
                const int col = nt * 8 + t4 * 2;
                if (col     > rowg)     s[nt][0] = -1e30f;
                if (col + 1 > rowg)     s[nt][1] = -1e30f;
                if (col     > rowg + 8) s[nt][2] = -1e30f;
                if (col + 1 > rowg + 8) s[nt][3] = -1e30f;
            }
        }

        #pragma unroll
        for (int r = 0; r < 2; ++r) {
            float mx = -1e30f;
            #pragma unroll
            for (int nt = 0; nt < 8; ++nt)
                mx = fmaxf(mx, fmaxf(s[nt][2 * r], s[nt][2 * r + 1]));
            mx = fmaxf(mx, __shfl_xor_sync(0xffffffffu, mx, 1));
            mx = fmaxf(mx, __shfl_xor_sync(0xffffffffu, mx, 2));
            const float mold = r ? m1 : m0;
            const float mnew = fmaxf(mold, mx);
            const float sc = __expf(mold - mnew);
            float sum = 0.0f;
            #pragma unroll
            for (int nt = 0; nt < 8; ++nt) {
                float p0 = __expf(s[nt][2 * r] - mnew);
                float p1 = __expf(s[nt][2 * r + 1] - mnew);
                s[nt][2 * r] = p0; s[nt][2 * r + 1] = p1;
                sum += p0 + p1;
            }
            sum += __shfl_xor_sync(0xffffffffu, sum, 1);
            sum += __shfl_xor_sync(0xffffffffu, sum, 2);
            if (r == 0) { l0 = l0 * sc + sum; m0 = mnew; }
            else        { l1 = l1 * sc + sum; m1 = mnew; }
            #pragma unroll
            for (int nt = 0; nt < 16; ++nt) {
                o[nt][2 * r]     *= sc;
                o[nt][2 * r + 1] *= sc;
            }
        }

        #pragma unroll
        for (int nt = 0; nt < 8; ++nt) {
            *(__half2*)(sm + OFF_P + ((w * 16 + g)     * PSTR + nt * 8 + t4 * 2) * 2) =
                __floats2half2_rn(s[nt][0], s[nt][1]);
            *(__half2*)(sm + OFF_P + ((w * 16 + g + 8) * PSTR + nt * 8 + t4 * 2) * 2) =
                __floats2half2_rn(s[nt][2], s[nt][3]);
        }
        __syncwarp();

        #pragma unroll
        for (int ks2 = 0; ks2 < 4; ++ks2) {
            uint32_t a[4];
            ldmx4(a, Ps + aoffP + ks2 * 32);
            #pragma unroll
            for (int j = 0; j < 8; ++j) {
                uint32_t r4[4];
                ldmx4(r4, Vs + boffV + j * 16 * VSTR * 2 + ks2 * 32);
                mma_f16(o[2 * j], a, r4);
                mma_f16(o[2 * j + 1], a, r4 + 2);
            }
        }
        __syncwarp();
    }

    const float i0 = 1.0f / l0, i1 = 1.0f / l1;
    const int tg = q0 + w * 16 + g;
    #pragma unroll
    for (int nt = 0; nt < 16; ++nt) {
        const int col = h * DH + dh * 128 + nt * 8 + t4 * 2;
        *(__half2*)&Og[(size_t)tg * Q_SIZE + col] =
            __floats2half2_rn(o[nt][0] * i0, o[nt][1] * i0);
        *(__half2*)&Og[(size_t)(tg + 8) * Q_SIZE + col] =
            __floats2half2_rn(o[nt][2] * i1, o[nt][3] * i1);
    }
}

// ---------------------------------------------------------------------------
// Elementwise fp32 -> fp16 convert
// ---------------------------------------------------------------------------
__global__ __launch_bounds__(256)
void convert_h_kernel(const float* __restrict__ in, __half* __restrict__ out, int n)
{
    int i = (blockIdx.x * 256 + threadIdx.x) * 4;
    if (i < n) {
        float4 v = *(const float4*)&in[i];
        *(__half2*)&out[i]     = __floats2half2_rn(v.x, v.y);
        *(__half2*)&out[i + 2] = __floats2half2_rn(v.z, v.w);
    }
}

// ---------------------------------------------------------------------------
// Fast fp32->fp16 transpose, 64x64 tiles: out[C,R] = (half)in[R,C]^T
// float4 loads, half2 stores. R, C multiples of 64.
// ---------------------------------------------------------------------------
__global__ __launch_bounds__(256)
void transpose_f2h(const float* __restrict__ in, __half* __restrict__ out, int R, int C)
{
    __shared__ float tile[64][65];
    const int c0 = blockIdx.x * 64, r0 = blockIdx.y * 64;
    const int tid = threadIdx.x;
    const int lx = tid & 15;       // float4 column group
    const int ly = tid >> 4;       // row 0..15
    #pragma unroll
    for (int i = 0; i < 4; i++) {
        const int r = ly + i * 16;
        float4 v = *(const float4*)&in[(size_t)(r0 + r) * C + c0 + lx * 4];
        tile[lx * 4 + 0][r] = v.x;
        tile[lx * 4 + 1][r] = v.y;
        tile[lx * 4 + 2][r] = v.z;
        tile[lx * 4 + 3][r] = v.w;
    }
    __syncthreads();
    const int wx = tid & 31;       // r-pair index
    const int wy = tid >> 5;       // c 0..7
    #pragma unroll
    for (int i = 0; i < 8; i++) {
        const int c = wy + i * 8;
        *(__half2*)&out[(size_t)(c0 + c) * R + r0 + wx * 2] =
            __floats2half2_rn(tile[c][wx * 2], tile[c][wx * 2 + 1]);
    }
}

// ---------------------------------------------------------------------------
// Generic tiled transpose (kept for half V)
// ---------------------------------------------------------------------------
template<typename Tin, typename Tout>
__global__ __launch_bounds__(256)
void transpose_kernel(const Tin* __restrict__ in, Tout* __restrict__ out, int R, int C)
{
    __shared__ float tile[32][33];
    const int c0 = blockIdx.x * 32, r0 = blockIdx.y * 32;
    const int x = threadIdx.x, y = threadIdx.y;
    #pragma unroll
    for (int i = 0; i < 32; i += 8)
        tile[y + i][x] = (float)in[(size_t)(r0 + y + i) * C + c0 + x];
    __syncthreads();
    #pragma unroll
    for (int i = 0; i < 32; i += 8)
        out[(size_t)(c0 + y + i) * R + r0 + x] = (Tout)tile[x][y + i];
}

// ---------------------------------------------------------------------------
// Fused RMSNorm + NeoX RoPE, warp-per-(t,h)
// ---------------------------------------------------------------------------
__global__ __launch_bounds__(128)
void normrope_kernel(const float* __restrict__ qkv,
                     const int*   __restrict__ positions,
                     const float* __restrict__ qw,
                     const float* __restrict__ kw,
                     __half* __restrict__ q_out,
                     __half* __restrict__ k_out,
                     __half* __restrict__ v_out)
{
    const int wg = blockIdx.x * 4 + (threadIdx.x >> 5);
    const int t = wg >> 4, h = wg & 15;
    const int lane = threadIdx.x & 31;
    const int pos = positions[t];
    const size_t row = (size_t)t * QKV_N;
    const size_t obase = (size_t)t * Q_SIZE + h * DH;

    float c[4], sn[4];
    #pragma unroll
    for (int i = 0; i < 4; i++) {
        const float fi = (float)(lane + 32 * i);
        const float fr = expf(-fi * (LN_THETA / 128.0f));
        sincosf((float)pos * fr, &sn[i], &c[i]);
    }

    #pragma unroll
    for (int sec = 0; sec < 3; sec++) {
        const size_t base = row + sec * Q_SIZE + h * DH;
        float x[8];
        #pragma unroll
        for (int i = 0; i < 8; i++) x[i] = qkv[base + lane + 32 * i];
        float ss = 0.0f;
        #pragma unroll
        for (int i = 0; i < 8; i++) ss += x[i] * x[i];
        #pragma unroll
        for (int off = 16; off > 0; off >>= 1) ss += __shfl_xor_sync(0xffffffffu, ss, off);
        const float rs = rsqrtf(ss * (1.0f / DH) + EPS);

        float v[8];
        #pragma unroll
        for (int i = 0; i < 8; i++) {
            float w = 1.0f;
            if (sec == 0) w = qw[lane + 32 * i];
            else if (sec == 1) w = kw[lane + 32 * i];
            v[i] = x[i] * rs * w;
        }
        if (sec < 2) {
            __half* outp = sec == 0 ? q_out : k_out;
            #pragma unroll
            for (int i = 0; i < 4; i++) {
                outp[obase + lane + 32 * i]       = __float2half(v[i] * c[i] - v[i + 4] * sn[i]);
                outp[obase + lane + 32 * i + 128] = __float2half(v[i + 4] * c[i] + v[i] * sn[i]);
            }
        } else {
            #pragma unroll
            for (int i = 0; i < 8; i++)
                v_out[obase + lane + 32 * i] = __float2half(v[i]);
        }
    }
}

// ---------------------------------------------------------------------------
// Launch
// ---------------------------------------------------------------------------
extern "C" void kernel_launch(void* const* d_in, const int* in_sizes, int n_in,
                              void* d_out, int out_size)
{
    const float* hidden    = (const float*)d_in[0];
    const int*   positions = (const int*)  d_in[1];
    const float* w_qkv     = (const float*)d_in[2];
    const float* w_o       = (const float*)d_in[3];
    const float* qw        = (const float*)d_in[4];
    const float* kw        = (const float*)d_in[5];
    float* out = (float*)d_out;

    __half *hid_h, *wqkv_h, *wo_h, *qh, *kh, *vh, *vth, *attn_h;
    float *qkv;
    cudaGetSymbolAddress((void**)&hid_h,  g_hidden_h);
    cudaGetSymbolAddress((void**)&wqkv_h, g_wqkv_h);
    cudaGetSymbolAddress((void**)&wo_h,   g_wo_h);
    cudaGetSymbolAddress((void**)&qkv,    g_qkv);
    cudaGetSymbolAddress((void**)&qh,     g_qh);
    cudaGetSymbolAddress((void**)&kh,     g_kh);
    cudaGetSymbolAddress((void**)&vh,     g_vh);
    cudaGetSymbolAddress((void**)&vth,    g_vth);
    cudaGetSymbolAddress((void**)&attn_h, g_attn_h);

    cudaFuncSetAttribute(h_gemm<false, false, false>, cudaFuncAttributeMaxDynamicSharedMemorySize, SMEM_BYTES);
    cudaFuncSetAttribute(flash_kernel, cudaFuncAttributeMaxDynamicSharedMemorySize, FLASH_SMEM);

    // 0) operand conversions / transposes
    convert_h_kernel<<<(T_SEQ * HID / 4 + 255) / 256, 256>>>(hidden, hid_h, T_SEQ * HID);
    transpose_f2h<<<dim3(QKV_N / 64, HID / 64), 256>>>(w_qkv, wqkv_h, HID, QKV_N);
    transpose_f2h<<<dim3(HID / 64,   HID / 64), 256>>>(w_o,   wo_h,   HID, HID);

    // 1) qkv = hidden @ w_qkv  (fp32 out for exact rmsnorm)
    h_gemm<false, false, false><<<dim3(QKV_N / BN, T_SEQ / BM, 1), 256, SMEM_BYTES>>>(
        hid_h, wqkv_h, qkv, T_SEQ, QKV_N, HID, HID, HID, QKV_N, 0, 0, 0);

    // 2) rmsnorm + rope -> fp16 q/k/v
    normrope_kernel<<<T_SEQ * NH / 4, 128>>>(qkv, positions, qw, kw, qh, kh, vh);

    // 2b) transpose V -> [NH*DH, T] fp16
    transpose_kernel<__half, __half><<<dim3((NH * DH) / 32, T_SEQ / 32), dim3(32, 8)>>>(vh, vth, T_SEQ, NH * DH);

    // 3) fused causal attention -> attn_h fp16
    flash_kernel<<<dim3(T_SEQ / FQ, NH, 2), 128, FLASH_SMEM>>>(qh, kh, vth, attn_h);

    // 4) out = attn @ w_o (fp32 out)
    h_gemm<false, false, false><<<dim3(HID / BN, T_SEQ / BM, 1), 256, SMEM_BYTES>>>(
        attn_h, wo_h, out, T_SEQ, HID, Q_SIZE, Q_SIZE, Q_SIZE, HID, 0, 0, 0);

    (void)in_sizes; (void)n_in; (void)out_size;
}

// round 9
// speedup vs baseline: 1.5466x; 1.0051x over previous
#include <cuda_runtime.h>
#include <cuda_fp16.h>
#include <math.h>
#include <float.h>
#include <cstdint>

// Problem constants
#define T_SEQ 2048
#define HID   4096
#define NH    16
#define DH    256
#define QKV_N (3 * NH * DH)      // 12288
#define Q_SIZE (NH * DH)         // 4096
#define EPS   1e-6f
#define LN_THETA 9.210340371976184f   // ln(10000)

// GEMM tile config (fp16 engine): CTA 128x128, warp 32x64, 8 warps, BK=64
#define BM 128
#define BN 128
#define BK 64
#define STRIDE 72
#define STAGES 3
#define STAGE_BYTES ((BM + BN) * STRIDE * 2)   // 36864
#define SMEM_BYTES (STAGES * STAGE_BYTES)      // 110592

// Flash v2 config: q-tile 128, kv-tile 64, 8 warps, d split in 2, K/V double-buffered
#define FQM 128
#define FKV 64
#define QSTR 264                   // 256 + 8 pad (halfs)
#define VSTR 72                    // 64 + 8 pad
#define FOFF_K0 (FQM * QSTR * 2)               // 67584
#define FK_BYTES (FKV * QSTR * 2)              // 33792
#define FOFF_V0 (FOFF_K0 + 2 * FK_BYTES)       // 135168
#define FV_BYTES (128 * VSTR * 2)              // 18432
#define FLASH_SMEM (FOFF_V0 + 2 * FV_BYTES)    // 172032

// ---------------------------------------------------------------------------
// Scratch (static device globals)
// ---------------------------------------------------------------------------
__device__ __half g_hidden_h[(size_t)T_SEQ * HID];
__device__ __half g_wqkv_h[(size_t)QKV_N * HID];
__device__ __half g_wo_h[(size_t)HID * Q_SIZE];
__device__ float  g_qkv[(size_t)T_SEQ * QKV_N];
__device__ __half g_qh[(size_t)T_SEQ * NH * DH];
__device__ __half g_kh[(size_t)T_SEQ * NH * DH];
__device__ __half g_vh[(size_t)T_SEQ * NH * DH];
__device__ __half g_vth[(size_t)NH * DH * T_SEQ];
__device__ __half g_attn_h[(size_t)T_SEQ * NH * DH];

// ---------------------------------------------------------------------------
// PTX helpers
// ---------------------------------------------------------------------------
__device__ __forceinline__ uint32_t smem_u32(const void* p) {
    uint32_t a;
    asm("{ .reg .u64 t; cvta.to.shared.u64 t, %1; cvt.u32.u64 %0, t; }" : "=r"(a) : "l"(p));
    return a;
}
#define CP_ASYNC16(dst, src) \
    asm volatile("cp.async.cg.shared.global [%0], [%1], 16;" :: "r"(dst), "l"(src))
#define CP_COMMIT() asm volatile("cp.async.commit_group;" ::: "memory")
#define CP_WAIT(n)  asm volatile("cp.async.wait_group %0;" :: "n"(n) : "memory")

__device__ __forceinline__ void ldmx4(uint32_t* r, uint32_t addr) {
    asm volatile("ldmatrix.sync.aligned.m8n8.x4.shared.b16 {%0,%1,%2,%3}, [%4];"
        : "=r"(r[0]), "=r"(r[1]), "=r"(r[2]), "=r"(r[3]) : "r"(addr));
}
__device__ __forceinline__ void mma_f16(float* d, const uint32_t* a, const uint32_t* b) {
    asm volatile(
        "mma.sync.aligned.m16n8k16.row.col.f32.f16.f16.f32 "
        "{%0,%1,%2,%3}, {%4,%5,%6,%7}, {%8,%9}, {%0,%1,%2,%3};"
        : "+f"(d[0]), "+f"(d[1]), "+f"(d[2]), "+f"(d[3])
        : "r"(a[0]), "r"(a[1]), "r"(a[2]), "r"(a[3]), "r"(b[0]), "r"(b[1]));
}
__device__ __forceinline__ uint32_t h2pack(float a, float b) {
    __half2 h = __floats2half2_rn(a, b);
    return *(uint32_t*)&h;
}

// ---------------------------------------------------------------------------
// fp16 mma.sync GEMM (unchanged from R8)
// ---------------------------------------------------------------------------
template<bool CSKIP, bool CKLIM, bool HALF_OUT>
__global__ __launch_bounds__(256, 2)
void h_gemm(const __half* __restrict__ A, const __half* __restrict__ B, void* __restrict__ Cv,
            int M, int N, int K, int lda, int ldb, int ldc,
            long long bA, long long bB, long long bC)
{
    const int row0 = blockIdx.y * BM;
    const int col0 = blockIdx.x * BN;
    if (CSKIP && col0 >= row0 + BM) return;
    const int Keff = CKLIM ? min(K, row0 + BM) : K;
    const int nCh = Keff / BK;

    A += (long long)blockIdx.z * bA;
    B += (long long)blockIdx.z * bB;

    extern __shared__ char smem[];
    const uint32_t sbase = smem_u32(smem);

    const int tid = threadIdx.x;
    const int wid = tid >> 5, lane = tid & 31;
    const int g = lane >> 2, t4 = lane & 3;
    const int warpM = (wid & 3) * 32;
    const int warpN = (wid >> 2) * 64;
    const int lrow = lane & 7, lsel = lane >> 3;

    const uint32_t aoff = ((warpM + (lsel & 1) * 8 + lrow) * STRIDE + (lsel >> 1) * 8) * 2;
    const uint32_t boff = ((warpN + (lsel >> 1) * 8 + lrow) * STRIDE + (lsel & 1) * 8) * 2;

    float acc[2][8][4];
    #pragma unroll
    for (int i = 0; i < 2; i++)
        #pragma unroll
        for (int j = 0; j < 8; j++)
            #pragma unroll
            for (int q = 0; q < 4; q++) acc[i][j][q] = 0.0f;

    auto load_stage = [&](int st, int ch) {
        const uint32_t sA = sbase + st * STAGE_BYTES;
        const uint32_t sB = sA + BM * STRIDE * 2;
        const int k0 = ch * BK;
        #pragma unroll
        for (int i = 0; i < 4; i++) {
            int u = tid + i * 256;
            int r = u >> 3, cu = u & 7;
            CP_ASYNC16(sA + (r * STRIDE + cu * 8) * 2,
                       &A[(size_t)(row0 + r) * lda + k0 + cu * 8]);
        }
        #pragma unroll
        for (int i = 0; i < 4; i++) {
            int u = tid + i * 256;
            int r = u >> 3, cu = u & 7;
            CP_ASYNC16(sB + (r * STRIDE + cu * 8) * 2,
                       &B[(size_t)(col0 + r) * ldb + k0 + cu * 8]);
        }
    };

    auto compute_k16 = [&](uint32_t sA, uint32_t sB, int kk) {
        uint32_t a[2][4];
        ldmx4(a[0], sA + aoff + kk * 32);
        ldmx4(a[1], sA + aoff + 16 * STRIDE * 2 + kk * 32);
        uint32_t b[8][2];
        #pragma unroll
        for (int j = 0; j < 4; ++j) {
            uint32_t r[4];
            ldmx4(r, sB + boff + j * 16 * STRIDE * 2 + kk * 32);
            b[2 * j][0] = r[0]; b[2 * j][1] = r[1];
            b[2 * j + 1][0] = r[2]; b[2 * j + 1][1] = r[3];
        }
        #pragma unroll
        for (int nt = 0; nt < 8; ++nt) {
            mma_f16(acc[0][nt], a[0], b[nt]);
            mma_f16(acc[1][nt], a[1], b[nt]);
        }
    };

    #pragma unroll
    for (int p = 0; p < STAGES - 1; ++p) {
        if (p < nCh) load_stage(p, p);
        CP_COMMIT();
    }

    for (int c = 0; c < nCh; ++c) {
        CP_WAIT(STAGES - 2);
        __syncthreads();

        const uint32_t sA = sbase + (c % STAGES) * STAGE_BYTES;
        const uint32_t sB = sA + BM * STRIDE * 2;

        compute_k16(sA, sB, 0);
        if (c + STAGES - 1 < nCh) load_stage((c + STAGES - 1) % STAGES, c + STAGES - 1);
        CP_COMMIT();
        #pragma unroll
        for (int kk = 1; kk < 4; ++kk)
            compute_k16(sA, sB, kk);
    }

    #pragma unroll
    for (int mt = 0; mt < 2; mt++) {
        const int r0 = row0 + warpM + mt * 16 + g;
        #pragma unroll
        for (int nt = 0; nt < 8; nt++) {
            const int cc = col0 + warpN + nt * 8 + t4 * 2;
            if (HALF_OUT) {
                __half* C = (__half*)Cv + (long long)blockIdx.z * bC;
                *(__half2*)&C[(size_t)r0 * ldc + cc] =
                    __floats2half2_rn(acc[mt][nt][0], acc[mt][nt][1]);
                *(__half2*)&C[(size_t)(r0 + 8) * ldc + cc] =
                    __floats2half2_rn(acc[mt][nt][2], acc[mt][nt][3]);
            } else {
                float* C = (float*)Cv + (long long)blockIdx.z * bC;
                *(float2*)&C[(size_t)r0 * ldc + cc]       = make_float2(acc[mt][nt][0], acc[mt][nt][1]);
                *(float2*)&C[(size_t)(r0 + 8) * ldc + cc] = make_float2(acc[mt][nt][2], acc[mt][nt][3]);
            }
        }
    }
}

// ---------------------------------------------------------------------------
// Flash v2: q-tile 128, 8 warps, register-P, double-buffered K/V.
//   CTA = (128 q rows, head, d-half). Warp w owns rows w*16..w*16+15.
// ---------------------------------------------------------------------------
__global__ __launch_bounds__(256, 1)
void flash_kernel(const __half* __restrict__ Qg, const __half* __restrict__ Kg,
                  const __half* __restrict__ Vt, __half* __restrict__ Og)
{
    const int qtile = gridDim.x - 1 - blockIdx.x;   // longest work first
    const int q0 = qtile * FQM;
    const int h  = blockIdx.y;
    const int dh = blockIdx.z;

    extern __shared__ char sm[];
    const uint32_t sb = smem_u32(sm);
    const uint32_t Qs = sb;

    const int tid = threadIdx.x;
    const int w = tid >> 5, lane = tid & 31;
    const int g = lane >> 2, t4 = lane & 3;
    const int lrow = lane & 7, lsel = lane >> 3;

    const __half* Qp = Qg + (size_t)h * DH;
    const __half* Kp = Kg + (size_t)h * DH;
    const __half* Vp = Vt + (size_t)(h * DH + dh * 128) * T_SEQ;

    // Q tile (128 x 256): 4096 16B-units, 16 per thread
    #pragma unroll
    for (int i = 0; i < 16; i++) {
        int u = tid + i * 256;
        int r = u >> 5, cu = u & 31;
        CP_ASYNC16(Qs + (r * QSTR + cu * 8) * 2, Qp + (size_t)(q0 + r) * Q_SIZE + cu * 8);
    }

    auto load_kv = [&](int buf, int kv0) {
        const uint32_t Ks = sb + FOFF_K0 + buf * FK_BYTES;
        const uint32_t Vs = sb + FOFF_V0 + buf * FV_BYTES;
        #pragma unroll
        for (int i = 0; i < 8; i++) {
            int u = tid + i * 256;
            int r = u >> 5, cu = u & 31;
            CP_ASYNC16(Ks + (r * QSTR + cu * 8) * 2, Kp + (size_t)(kv0 + r) * Q_SIZE + cu * 8);
        }
        #pragma unroll
        for (int i = 0; i < 4; i++) {
            int u = tid + i * 256;
            int r = u >> 3, cu = u & 7;
            CP_ASYNC16(Vs + (r * VSTR + cu * 8) * 2, Vp + (size_t)r * T_SEQ + kv0 + cu * 8);
        }
    };

    const uint32_t aoffQ = ((w * 16 + (lsel & 1) * 8 + lrow) * QSTR + (lsel >> 1) * 8) * 2;
    const uint32_t boffK = (((lsel >> 1) * 8 + lrow) * QSTR + (lsel & 1) * 8) * 2;
    const uint32_t boffV = (((lsel >> 1) * 8 + lrow) * VSTR + (lsel & 1) * 8) * 2;

    float m0 = -1e30f, m1 = -1e30f, l0 = 0.0f, l1 = 0.0f;
    float o[16][4];
    #pragma unroll
    for (int i = 0; i < 16; i++)
        #pragma unroll
        for (int q = 0; q < 4; q++) o[i][q] = 0.0f;

    const int nkv = 2 * qtile + 2;
    load_kv(0, 0);                  // prologue: Q + KV(0) in one group
    CP_COMMIT();

    for (int it = 0; it < nkv; ++it) {
        const int kv0 = it * FKV;
        CP_WAIT(0);                 // current buffer (and Q on it=0) resident
        __syncthreads();            // everyone done reading buf (it+1)&1 from iter it-1
        if (it + 1 < nkv) load_kv((it + 1) & 1, kv0 + FKV);
        CP_COMMIT();                // overlaps with compute below

        const uint32_t Ks = sb + FOFF_K0 + (it & 1) * FK_BYTES;
        const uint32_t Vs = sb + FOFF_V0 + (it & 1) * FV_BYTES;

        // warp fully above the diagonal? skip (no barriers inside body)
        if (kv0 > q0 + w * 16 + 15) continue;

        // S = Q K^T  (16 q rows x 64 kv cols per warp)
        float s[8][4];
        #pragma unroll
        for (int i = 0; i < 8; i++)
            #pragma unroll
            for (int q = 0; q < 4; q++) s[i][q] = 0.0f;
        #pragma unroll
        for (int ks = 0; ks < 16; ++ks) {
            uint32_t a[4];
            ldmx4(a, Qs + aoffQ + ks * 32);
            #pragma unroll
            for (int j = 0; j < 4; ++j) {
                uint32_t r4[4];
                ldmx4(r4, Ks + boffK + j * 16 * QSTR * 2 + ks * 32);
                mma_f16(s[2 * j], a, r4);
                mma_f16(s[2 * j + 1], a, r4 + 2);
            }
        }

        // causal mask if this tile can cross the diagonal for this warp
        if (kv0 + FKV - 1 > q0 + w * 16) {
            const int rowg = q0 + w * 16 + g;
            #pragma unroll
            for (int nt = 0; nt < 8; ++nt) {
                const int col = kv0 + nt * 8 + t4 * 2;
                if (col     > rowg)     s[nt][0] = -1e30f;
                if (col + 1 > rowg)     s[nt][1] = -1e30f;
                if (col     > rowg + 8) s[nt][2] = -1e30f;
                if (col + 1 > rowg + 8) s[nt][3] = -1e30f;
            }
        }

        // online softmax, rows g (r=0) and g+8 (r=1)
        #pragma unroll
        for (int r = 0; r < 2; ++r) {
            float mx = -1e30f;
            #pragma unroll
            for (int nt = 0; nt < 8; ++nt)
                mx = fmaxf(mx, fmaxf(s[nt][2 * r], s[nt][2 * r + 1]));
            mx = fmaxf(mx, __shfl_xor_sync(0xffffffffu, mx, 1));
            mx = fmaxf(mx, __shfl_xor_sync(0xffffffffu, mx, 2));
            const float mold = r ? m1 : m0;
            const float mnew = fmaxf(mold, mx);
            const float sc = __expf(mold - mnew);
            float sum = 0.0f;
            #pragma unroll
            for (int nt = 0; nt < 8; ++nt) {
                float p0 = __expf(s[nt][2 * r] - mnew);
                float p1 = __expf(s[nt][2 * r + 1] - mnew);
                s[nt][2 * r] = p0; s[nt][2 * r + 1] = p1;
                sum += p0 + p1;
            }
            sum += __shfl_xor_sync(0xffffffffu, sum, 1);
            sum += __shfl_xor_sync(0xffffffffu, sum, 2);
            if (r == 0) { l0 = l0 * sc + sum; m0 = mnew; }
            else        { l1 = l1 * sc + sum; m1 = mnew; }
            #pragma unroll
            for (int nt = 0; nt < 16; ++nt) {
                o[nt][2 * r]     *= sc;
                o[nt][2 * r + 1] *= sc;
            }
        }

        // O += P V with P straight from S registers (C-frag == A-frag layout)
        #pragma unroll
        for (int ks2 = 0; ks2 < 4; ++ks2) {
            uint32_t a[4];
            a[0] = h2pack(s[2 * ks2][0],     s[2 * ks2][1]);
            a[1] = h2pack(s[2 * ks2][2],     s[2 * ks2][3]);
            a[2] = h2pack(s[2 * ks2 + 1][0], s[2 * ks2 + 1][1]);
            a[3] = h2pack(s[2 * ks2 + 1][2], s[2 * ks2 + 1][3]);
            #pragma unroll
            for (int j = 0; j < 8; ++j) {
                uint32_t r4[4];
                ldmx4(r4, Vs + boffV + j * 16 * VSTR * 2 + ks2 * 32);
                mma_f16(o[2 * j], a, r4);
                mma_f16(o[2 * j + 1], a, r4 + 2);
            }
        }
    }

    const float i0 = 1.0f / l0, i1 = 1.0f / l1;
    const int tg = q0 + w * 16 + g;
    #pragma unroll
    for (int nt = 0; nt < 16; ++nt) {
        const int col = h * DH + dh * 128 + nt * 8 + t4 * 2;
        *(__half2*)&Og[(size_t)tg * Q_SIZE + col] =
            __floats2half2_rn(o[nt][0] * i0, o[nt][1] * i0);
        *(__half2*)&Og[(size_t)(tg + 8) * Q_SIZE + col] =
            __floats2half2_rn(o[nt][2] * i1, o[nt][3] * i1);
    }
}

// ---------------------------------------------------------------------------
// Elementwise fp32 -> fp16 convert
// ---------------------------------------------------------------------------
__global__ __launch_bounds__(256)
void convert_h_kernel(const float* __restrict__ in, __half* __restrict__ out, int n)
{
    int i = (blockIdx.x * 256 + threadIdx.x) * 4;
    if (i < n) {
        float4 v = *(const float4*)&in[i];
        *(__half2*)&out[i]     = __floats2half2_rn(v.x, v.y);
        *(__half2*)&out[i + 2] = __floats2half2_rn(v.z, v.w);
    }
}

// ---------------------------------------------------------------------------
// Fast fp32->fp16 transpose, 64x64 tiles
// ---------------------------------------------------------------------------
__global__ __launch_bounds__(256)
void transpose_f2h(const float* __restrict__ in, __half* __restrict__ out, int R, int C)
{
    __shared__ float tile[64][65];
    const int c0 = blockIdx.x * 64, r0 = blockIdx.y * 64;
    const int tid = threadIdx.x;
    const int lx = tid & 15;
    const int ly = tid >> 4;
    #pragma unroll
    for (int i = 0; i < 4; i++) {
        const int r = ly + i * 16;
        float4 v = *(const float4*)&in[(size_t)(r0 + r) * C + c0 + lx * 4];
        tile[lx * 4 + 0][r] = v.x;
        tile[lx * 4 + 1][r] = v.y;
        tile[lx * 4 + 2][r] = v.z;
        tile[lx * 4 + 3][r] = v.w;
    }
    __syncthreads();
    const int wx = tid & 31;
    const int wy = tid >> 5;
    #pragma unroll
    for (int i = 0; i < 8; i++) {
        const int c = wy + i * 8;
        *(__half2*)&out[(size_t)(c0 + c) * R + r0 + wx * 2] =
            __floats2half2_rn(tile[c][wx * 2], tile[c][wx * 2 + 1]);
    }
}

// ---------------------------------------------------------------------------
// Generic tiled transpose (half V)
// ---------------------------------------------------------------------------
template<typename Tin, typename Tout>
__global__ __launch_bounds__(256)
void transpose_kernel(const Tin* __restrict__ in, Tout* __restrict__ out, int R, int C)
{
    __shared__ float tile[32][33];
    const int c0 = blockIdx.x * 32, r0 = blockIdx.y * 32;
    const int x = threadIdx.x, y = threadIdx.y;
    #pragma unroll
    for (int i = 0; i < 32; i += 8)
        tile[y + i][x] = (float)in[(size_t)(r0 + y + i) * C + c0 + x];
    __syncthreads();
    #pragma unroll
    for (int i = 0; i < 32; i += 8)
        out[(size_t)(c0 + y + i) * R + r0 + x] = (Tout)tile[x][y + i];
}

// ---------------------------------------------------------------------------
// Fused RMSNorm + NeoX RoPE, warp-per-(t,h)
// ---------------------------------------------------------------------------
__global__ __launch_bounds__(128)
void normrope_kernel(const float* __restrict__ qkv,
                     const int*   __restrict__ positions,
                     const float* __restrict__ qw,
                     const float* __restrict__ kw,
                     __half* __restrict__ q_out,
                     __half* __restrict__ k_out,
                     __half* __restrict__ v_out)
{
    const int wg = blockIdx.x * 4 + (threadIdx.x >> 5);
    const int t = wg >> 4, h = wg & 15;
    const int lane = threadIdx.x & 31;
    const int pos = positions[t];
    const size_t row = (size_t)t * QKV_N;
    const size_t obase = (size_t)t * Q_SIZE + h * DH;

    float c[4], sn[4];
    #pragma unroll
    for (int i = 0; i < 4; i++) {
        const float fi = (float)(lane + 32 * i);
        const float fr = expf(-fi * (LN_THETA / 128.0f));
        sincosf((float)pos * fr, &sn[i], &c[i]);
    }

    #pragma unroll
    for (int sec = 0; sec < 3; sec++) {
        const size_t base = row + sec * Q_SIZE + h * DH;
        float x[8];
        #pragma unroll
        for (int i = 0; i < 8; i++) x[i] = qkv[base + lane + 32 * i];
        float ss = 0.0f;
        #pragma unroll
        for (int i = 0; i < 8; i++) ss += x[i] * x[i];
        #pragma unroll
        for (int off = 16; off > 0; off >>= 1) ss += __shfl_xor_sync(0xffffffffu, ss, off);
        const float rs = rsqrtf(ss * (1.0f / DH) + EPS);

        float v[8];
        #pragma unroll
        for (int i = 0; i < 8; i++) {
            float w = 1.0f;
            if (sec == 0) w = qw[lane + 32 * i];
            else if (sec == 1) w = kw[lane + 32 * i];
            v[i] = x[i] * rs * w;
        }
        if (sec < 2) {
            __half* outp = sec == 0 ? q_out : k_out;
            #pragma unroll
            for (int i = 0; i < 4; i++) {
                outp[obase + lane + 32 * i]       = __float2half(v[i] * c[i] - v[i + 4] * sn[i]);
                outp[obase + lane + 32 * i + 128] = __float2half(v[i + 4] * c[i] + v[i] * sn[i]);
            }
        } else {
            #pragma unroll
            for (int i = 0; i < 8; i++)
                v_out[obase + lane + 32 * i] = __float2half(v[i]);
        }
    }
}

// ---------------------------------------------------------------------------
// Launch
// ---------------------------------------------------------------------------
extern "C" void kernel_launch(void* const* d_in, const int* in_sizes, int n_in,
                              void* d_out, int out_size)
{
    const float* hidden    = (const float*)d_in[0];
    const int*   positions = (const int*)  d_in[1];
    const float* w_qkv     = (const float*)d_in[2];
    const float* w_o       = (const float*)d_in[3];
    const float* qw        = (const float*)d_in[4];
    const float* kw        = (const float*)d_in[5];
    float* out = (float*)d_out;

    __half *hid_h, *wqkv_h, *wo_h, *qh, *kh, *vh, *vth, *attn_h;
    float *qkv;
    cudaGetSymbolAddress((void**)&hid_h,  g_hidden_h);
    cudaGetSymbolAddress((void**)&wqkv_h, g_wqkv_h);
    cudaGetSymbolAddress((void**)&wo_h,   g_wo_h);
    cudaGetSymbolAddress((void**)&qkv,    g_qkv);
    cudaGetSymbolAddress((void**)&qh,     g_qh);
    cudaGetSymbolAddress((void**)&kh,     g_kh);
    cudaGetSymbolAddress((void**)&vh,     g_vh);
    cudaGetSymbolAddress((void**)&vth,    g_vth);
    cudaGetSymbolAddress((void**)&attn_h, g_attn_h);

    cudaFuncSetAttribute(h_gemm<false, false, false>, cudaFuncAttributeMaxDynamicSharedMemorySize, SMEM_BYTES);
    cudaFuncSetAttribute(flash_kernel, cudaFuncAttributeMaxDynamicSharedMemorySize, FLASH_SMEM);

    // 0) operand conversions / transposes
    convert_h_kernel<<<(T_SEQ * HID / 4 + 255) / 256, 256>>>(hidden, hid_h, T_SEQ * HID);
    transpose_f2h<<<dim3(QKV_N / 64, HID / 64), 256>>>(w_qkv, wqkv_h, HID, QKV_N);
    transpose_f2h<<<dim3(HID / 64,   HID / 64), 256>>>(w_o,   wo_h,   HID, HID);

    // 1) qkv = hidden @ w_qkv  (fp32 out for exact rmsnorm)
    h_gemm<false, false, false><<<dim3(QKV_N / BN, T_SEQ / BM, 1), 256, SMEM_BYTES>>>(
        hid_h, wqkv_h, qkv, T_SEQ, QKV_N, HID, HID, HID, QKV_N, 0, 0, 0);

    // 2) rmsnorm + rope -> fp16 q/k/v
    normrope_kernel<<<T_SEQ * NH / 4, 128>>>(qkv, positions, qw, kw, qh, kh, vh);

    // 2b) transpose V -> [NH*DH, T] fp16
    transpose_kernel<__half, __half><<<dim3((NH * DH) / 32, T_SEQ / 32), dim3(32, 8)>>>(vh, vth, T_SEQ, NH * DH);

    // 3) fused causal attention -> attn_h fp16
    flash_kernel<<<dim3(T_SEQ / FQM, NH, 2), 256, FLASH_SMEM>>>(qh, kh, vth, attn_h);

    // 4) out = attn @ w_o (fp32 out)
    h_gemm<false, false, false><<<dim3(HID / BN, T_SEQ / BM, 1), 256, SMEM_BYTES>>>(
        attn_h, wo_h, out, T_SEQ, HID, Q_SIZE, Q_SIZE, Q_SIZE, HID, 0, 0, 0);

    (void)in_sizes; (void)n_in; (void)out_size;
}

// round 11
// speedup vs baseline: 1.6290x; 1.0533x over previous
#include <cuda_runtime.h>
#include <cuda_fp16.h>
#include <math.h>
#include <float.h>
#include <cstdint>

// Problem constants
#define T_SEQ 2048
#define HID   4096
#define NH    16
#define DH    256
#define QKV_N (3 * NH * DH)      // 12288
#define Q_SIZE (NH * DH)         // 4096
#define EPS   1e-6f
#define LN_THETA 9.210340371976184f   // ln(10000)

// GEMM tile config (fp16 engine): CTA 128x128, warp 32x64, 8 warps, BK=64
#define BM 128
#define BN 128
#define BK 64
#define STRIDE 72
#define STAGES 3
#define STAGE_BYTES ((BM + BN) * STRIDE * 2)   // 36864
#define SMEM_BYTES (STAGES * STAGE_BYTES)      // 110592

// Flash v3 config: q-tile 128, kv-tile 64, 8 warps, FULL D=256, K/V double-buffered
#define FQM 128
#define FKV 64
#define QSTR 264                   // 256 + 8 pad (halfs)
#define VSTR 72                    // 64 + 8 pad
#define FOFF_K0 (FQM * QSTR * 2)               // 67584
#define FK_BYTES (FKV * QSTR * 2)              // 33792
#define FOFF_V0 (FOFF_K0 + 2 * FK_BYTES)       // 135168
#define FV_BYTES (DH * VSTR * 2)               // 36864 (256 d-rows x 64 kv)
#define FLASH_SMEM (FOFF_V0 + 2 * FV_BYTES)    // 208896

// ---------------------------------------------------------------------------
// Scratch (static device globals)
// ---------------------------------------------------------------------------
__device__ __half g_hidden_h[(size_t)T_SEQ * HID];
__device__ __half g_wqkv_h[(size_t)QKV_N * HID];
__device__ __half g_wo_h[(size_t)HID * Q_SIZE];
__device__ float  g_qkv[(size_t)T_SEQ * QKV_N];
__device__ __half g_qh[(size_t)T_SEQ * NH * DH];
__device__ __half g_kh[(size_t)T_SEQ * NH * DH];
__device__ __half g_vh[(size_t)T_SEQ * NH * DH];
__device__ __half g_vth[(size_t)NH * DH * T_SEQ];
__device__ __half g_attn_h[(size_t)T_SEQ * NH * DH];

// ---------------------------------------------------------------------------
// PTX helpers
// ---------------------------------------------------------------------------
__device__ __forceinline__ uint32_t smem_u32(const void* p) {
    uint32_t a;
    asm("{ .reg .u64 t; cvta.to.shared.u64 t, %1; cvt.u32.u64 %0, t; }" : "=r"(a) : "l"(p));
    return a;
}
#define CP_ASYNC16(dst, src) \
    asm volatile("cp.async.cg.shared.global [%0], [%1], 16;" :: "r"(dst), "l"(src))
#define CP_COMMIT() asm volatile("cp.async.commit_group;" ::: "memory")
#define CP_WAIT(n)  asm volatile("cp.async.wait_group %0;" :: "n"(n) : "memory")

__device__ __forceinline__ void ldmx4(uint32_t* r, uint32_t addr) {
    asm volatile("ldmatrix.sync.aligned.m8n8.x4.shared.b16 {%0,%1,%2,%3}, [%4];"
        : "=r"(r[0]), "=r"(r[1]), "=r"(r[2]), "=r"(r[3]) : "r"(addr));
}
__device__ __forceinline__ void mma_f16(float* d, const uint32_t* a, const uint32_t* b) {
    asm volatile(
        "mma.sync.aligned.m16n8k16.row.col.f32.f16.f16.f32 "
        "{%0,%1,%2,%3}, {%4,%5,%6,%7}, {%8,%9}, {%0,%1,%2,%3};"
        : "+f"(d[0]), "+f"(d[1]), "+f"(d[2]), "+f"(d[3])
        : "r"(a[0]), "r"(a[1]), "r"(a[2]), "r"(a[3]), "r"(b[0]), "r"(b[1]));
}
__device__ __forceinline__ uint32_t h2pack(float a, float b) {
    __half2 h = __floats2half2_rn(a, b);
    return *(uint32_t*)&h;
}

// ---------------------------------------------------------------------------
// fp16 mma.sync GEMM (unchanged from R8)
// ---------------------------------------------------------------------------
template<bool CSKIP, bool CKLIM, bool HALF_OUT>
__global__ __launch_bounds__(256, 2)
void h_gemm(const __half* __restrict__ A, const __half* __restrict__ B, void* __restrict__ Cv,
            int M, int N, int K, int lda, int ldb, int ldc,
            long long bA, long long bB, long long bC)
{
    const int row0 = blockIdx.y * BM;
    const int col0 = blockIdx.x * BN;
    if (CSKIP && col0 >= row0 + BM) return;
    const int Keff = CKLIM ? min(K, row0 + BM) : K;
    const int nCh = Keff / BK;

    A += (long long)blockIdx.z * bA;
    B += (long long)blockIdx.z * bB;

    extern __shared__ char smem[];
    const uint32_t sbase = smem_u32(smem);

    const int tid = threadIdx.x;
    const int wid = tid >> 5, lane = tid & 31;
    const int g = lane >> 2, t4 = lane & 3;
    const int warpM = (wid & 3) * 32;
    const int warpN = (wid >> 2) * 64;
    const int lrow = lane & 7, lsel = lane >> 3;

    const uint32_t aoff = ((warpM + (lsel & 1) * 8 + lrow) * STRIDE + (lsel >> 1) * 8) * 2;
    const uint32_t boff = ((warpN + (lsel >> 1) * 8 + lrow) * STRIDE + (lsel & 1) * 8) * 2;

    float acc[2][8][4];
    #pragma unroll
    for (int i = 0; i < 2; i++)
        #pragma unroll
        for (int j = 0; j < 8; j++)
            #pragma unroll
            for (int q = 0; q < 4; q++) acc[i][j][q] = 0.0f;

    auto load_stage = [&](int st, int ch) {
        const uint32_t sA = sbase + st * STAGE_BYTES;
        const uint32_t sB = sA + BM * STRIDE * 2;
        const int k0 = ch * BK;
        #pragma unroll
        for (int i = 0; i < 4; i++) {
            int u = tid + i * 256;
            int r = u >> 3, cu = u & 7;
            CP_ASYNC16(sA + (r * STRIDE + cu * 8) * 2,
                       &A[(size_t)(row0 + r) * lda + k0 + cu * 8]);
        }
        #pragma unroll
        for (int i = 0; i < 4; i++) {
            int u = tid + i * 256;
            int r = u >> 3, cu = u & 7;
            CP_ASYNC16(sB + (r * STRIDE + cu * 8) * 2,
                       &B[(size_t)(col0 + r) * ldb + k0 + cu * 8]);
        }
    };

    auto compute_k16 = [&](uint32_t sA, uint32_t sB, int kk) {
        uint32_t a[2][4];
        ldmx4(a[0], sA + aoff + kk * 32);
        ldmx4(a[1], sA + aoff + 16 * STRIDE * 2 + kk * 32);
        uint32_t b[8][2];
        #pragma unroll
        for (int j = 0; j < 4; ++j) {
            uint32_t r[4];
            ldmx4(r, sB + boff + j * 16 * STRIDE * 2 + kk * 32);
            b[2 * j][0] = r[0]; b[2 * j][1] = r[1];
            b[2 * j + 1][0] = r[2]; b[2 * j + 1][1] = r[3];
        }
        #pragma unroll
        for (int nt = 0; nt < 8; ++nt) {
            mma_f16(acc[0][nt], a[0], b[nt]);
            mma_f16(acc[1][nt], a[1], b[nt]);
        }
    };

    #pragma unroll
    for (int p = 0; p < STAGES - 1; ++p) {
        if (p < nCh) load_stage(p, p);
        CP_COMMIT();
    }

    for (int c = 0; c < nCh; ++c) {
        CP_WAIT(STAGES - 2);
        __syncthreads();

        const uint32_t sA = sbase + (c % STAGES) * STAGE_BYTES;
        const uint32_t sB = sA + BM * STRIDE * 2;

        compute_k16(sA, sB, 0);
        if (c + STAGES - 1 < nCh) load_stage((c + STAGES - 1) % STAGES, c + STAGES - 1);
        CP_COMMIT();
        #pragma unroll
        for (int kk = 1; kk < 4; ++kk)
            compute_k16(sA, sB, kk);
    }

    #pragma unroll
    for (int mt = 0; mt < 2; mt++) {
        const int r0 = row0 + warpM + mt * 16 + g;
        #pragma unroll
        for (int nt = 0; nt < 8; nt++) {
            const int cc = col0 + warpN + nt * 8 + t4 * 2;
            if (HALF_OUT) {
                __half* C = (__half*)Cv + (long long)blockIdx.z * bC;
                *(__half2*)&C[(size_t)r0 * ldc + cc] =
                    __floats2half2_rn(acc[mt][nt][0], acc[mt][nt][1]);
                *(__half2*)&C[(size_t)(r0 + 8) * ldc + cc] =
                    __floats2half2_rn(acc[mt][nt][2], acc[mt][nt][3]);
            } else {
                float* C = (float*)Cv + (long long)blockIdx.z * bC;
                *(float2*)&C[(size_t)r0 * ldc + cc]       = make_float2(acc[mt][nt][0], acc[mt][nt][1]);
                *(float2*)&C[(size_t)(r0 + 8) * ldc + cc] = make_float2(acc[mt][nt][2], acc[mt][nt][3]);
            }
        }
    }
}

// ---------------------------------------------------------------------------
// Flash v3: q-tile 128, 8 warps, register-P, FULL D=256 per CTA (no S recompute).
//   CTA = (128 q rows, head). Warp w owns rows w*16..w*16+15.
// ---------------------------------------------------------------------------
__global__ __launch_bounds__(256, 1)
void flash_kernel(const __half* __restrict__ Qg, const __half* __restrict__ Kg,
                  const __half* __restrict__ Vt, __half* __restrict__ Og)
{
    const int qtile = gridDim.x - 1 - blockIdx.x;   // longest work first
    const int q0 = qtile * FQM;
    const int h  = blockIdx.y;

    extern __shared__ char sm[];
    const uint32_t sb = smem_u32(sm);
    const uint32_t Qs = sb;

    const int tid = threadIdx.x;
    const int w = tid >> 5, lane = tid & 31;
    const int g = lane >> 2, t4 = lane & 3;
    const int lrow = lane & 7, lsel = lane >> 3;

    const __half* Qp = Qg + (size_t)h * DH;
    const __half* Kp = Kg + (size_t)h * DH;
    const __half* Vp = Vt + (size_t)h * DH * T_SEQ;   // 256 d-rows

    // Q tile (128 x 256): 4096 16B-units, 16 per thread
    #pragma unroll
    for (int i = 0; i < 16; i++) {
        int u = tid + i * 256;
        int r = u >> 5, cu = u & 31;
        CP_ASYNC16(Qs + (r * QSTR + cu * 8) * 2, Qp + (size_t)(q0 + r) * Q_SIZE + cu * 8);
    }

    auto load_kv = [&](int buf, int kv0) {
        const uint32_t Ks = sb + FOFF_K0 + buf * FK_BYTES;
        const uint32_t Vs = sb + FOFF_V0 + buf * FV_BYTES;
        #pragma unroll
        for (int i = 0; i < 8; i++) {           // K: 64 rows x 256 halfs
            int u = tid + i * 256;
            int r = u >> 5, cu = u & 31;
            CP_ASYNC16(Ks + (r * QSTR + cu * 8) * 2, Kp + (size_t)(kv0 + r) * Q_SIZE + cu * 8);
        }
        #pragma unroll
        for (int i = 0; i < 8; i++) {           // V: 256 d-rows x 64 kv halfs
            int u = tid + i * 256;
            int r = u >> 3, cu = u & 7;
            CP_ASYNC16(Vs + (r * VSTR + cu * 8) * 2, Vp + (size_t)r * T_SEQ + kv0 + cu * 8);
        }
    };

    const uint32_t aoffQ = ((w * 16 + (lsel & 1) * 8 + lrow) * QSTR + (lsel >> 1) * 8) * 2;
    const uint32_t boffK = (((lsel >> 1) * 8 + lrow) * QSTR + (lsel & 1) * 8) * 2;
    const uint32_t boffV = (((lsel >> 1) * 8 + lrow) * VSTR + (lsel & 1) * 8) * 2;

    float m0 = -1e30f, m1 = -1e30f, l0 = 0.0f, l1 = 0.0f;
    float o[32][4];
    #pragma unroll
    for (int i = 0; i < 32; i++)
        #pragma unroll
        for (int q = 0; q < 4; q++) o[i][q] = 0.0f;

    const int nkv = 2 * qtile + 2;
    load_kv(0, 0);                  // prologue: Q + KV(0) in one group
    CP_COMMIT();

    for (int it = 0; it < nkv; ++it) {
        const int kv0 = it * FKV;
        CP_WAIT(0);                 // current buffer (and Q on it=0) resident
        __syncthreads();            // everyone done reading buf (it+1)&1 from iter it-1
        if (it + 1 < nkv) load_kv((it + 1) & 1, kv0 + FKV);
        CP_COMMIT();                // overlaps with compute below

        const uint32_t Ks = sb + FOFF_K0 + (it & 1) * FK_BYTES;
        const uint32_t Vs = sb + FOFF_V0 + (it & 1) * FV_BYTES;

        // warp fully above the diagonal? skip (no barriers inside body)
        if (kv0 > q0 + w * 16 + 15) continue;

        // S = Q K^T  (16 q rows x 64 kv cols per warp)
        float s[8][4];
        #pragma unroll
        for (int i = 0; i < 8; i++)
            #pragma unroll
            for (int q = 0; q < 4; q++) s[i][q] = 0.0f;
        #pragma unroll
        for (int ks = 0; ks < 16; ++ks) {
            uint32_t a[4];
            ldmx4(a, Qs + aoffQ + ks * 32);
            #pragma unroll
            for (int j = 0; j < 4; ++j) {
                uint32_t r4[4];
                ldmx4(r4, Ks + boffK + j * 16 * QSTR * 2 + ks * 32);
                mma_f16(s[2 * j], a, r4);
                mma_f16(s[2 * j + 1], a, r4 + 2);
            }
        }

        // causal mask if this tile can cross the diagonal for this warp
        if (kv0 + FKV - 1 > q0 + w * 16) {
            const int rowg = q0 + w * 16 + g;
            #pragma unroll
            for (int nt = 0; nt < 8; ++nt) {
                const int col = kv0 + nt * 8 + t4 * 2;
                if (col     > rowg)     s[nt][0] = -1e30f;
                if (col + 1 > rowg)     s[nt][1] = -1e30f;
                if (col     > rowg + 8) s[nt][2] = -1e30f;
                if (col + 1 > rowg + 8) s[nt][3] = -1e30f;
            }
        }

        // online softmax, rows g (r=0) and g+8 (r=1)
        #pragma unroll
        for (int r = 0; r < 2; ++r) {
            float mx = -1e30f;
            #pragma unroll
            for (int nt = 0; nt < 8; ++nt)
                mx = fmaxf(mx, fmaxf(s[nt][2 * r], s[nt][2 * r + 1]));
            mx = fmaxf(mx, __shfl_xor_sync(0xffffffffu, mx, 1));
            mx = fmaxf(mx, __shfl_xor_sync(0xffffffffu, mx, 2));
            const float mold = r ? m1 : m0;
            const float mnew = fmaxf(mold, mx);
            const float sc = __expf(mold - mnew);
            float sum = 0.0f;
            #pragma unroll
            for (int nt = 0; nt < 8; ++nt) {
                float p0 = __expf(s[nt][2 * r] - mnew);
                float p1 = __expf(s[nt][2 * r + 1] - mnew);
                s[nt][2 * r] = p0; s[nt][2 * r + 1] = p1;
                sum += p0 + p1;
            }
            sum += __shfl_xor_sync(0xffffffffu, sum, 1);
            sum += __shfl_xor_sync(0xffffffffu, sum, 2);
            if (r == 0) { l0 = l0 * sc + sum; m0 = mnew; }
            else        { l1 = l1 * sc + sum; m1 = mnew; }
            #pragma unroll
            for (int nt = 0; nt < 32; ++nt) {
                o[nt][2 * r]     *= sc;
                o[nt][2 * r + 1] *= sc;
            }
        }

        // O += P V with P straight from S registers (C-frag == A-frag layout)
        #pragma unroll
        for (int ks2 = 0; ks2 < 4; ++ks2) {
            uint32_t a[4];
            a[0] = h2pack(s[2 * ks2][0],     s[2 * ks2][1]);
            a[1] = h2pack(s[2 * ks2][2],     s[2 * ks2][3]);
            a[2] = h2pack(s[2 * ks2 + 1][0], s[2 * ks2 + 1][1]);
            a[3] = h2pack(s[2 * ks2 + 1][2], s[2 * ks2 + 1][3]);
            #pragma unroll
            for (int j = 0; j < 16; ++j) {      // full 256 d cols
                uint32_t r4[4];
                ldmx4(r4, Vs + boffV + j * 16 * VSTR * 2 + ks2 * 32);
                mma_f16(o[2 * j], a, r4);
                mma_f16(o[2 * j + 1], a, r4 + 2);
            }
        }
    }

    const float i0 = 1.0f / l0, i1 = 1.0f / l1;
    const int tg = q0 + w * 16 + g;
    #pragma unroll
    for (int nt = 0; nt < 32; ++nt) {
        const int col = h * DH + nt * 8 + t4 * 2;
        *(__half2*)&Og[(size_t)tg * Q_SIZE + col] =
            __floats2half2_rn(o[nt][0] * i0, o[nt][1] * i0);
        *(__half2*)&Og[(size_t)(tg + 8) * Q_SIZE + col] =
            __floats2half2_rn(o[nt][2] * i1, o[nt][3] * i1);
    }
}

// ---------------------------------------------------------------------------
// Elementwise fp32 -> fp16 convert
// ---------------------------------------------------------------------------
__global__ __launch_bounds__(256)
void convert_h_kernel(const float* __restrict__ in, __half* __restrict__ out, int n)
{
    int i = (blockIdx.x * 256 + threadIdx.x) * 4;
    if (i < n) {
        float4 v = *(const float4*)&in[i];
        *(__half2*)&out[i]     = __floats2half2_rn(v.x, v.y);
        *(__half2*)&out[i + 2] = __floats2half2_rn(v.z, v.w);
    }
}

// ---------------------------------------------------------------------------
// Fast fp32->fp16 transpose, 64x64 tiles
// ---------------------------------------------------------------------------
__global__ __launch_bounds__(256)
void transpose_f2h(const float* __restrict__ in, __half* __restrict__ out, int R, int C)
{
    __shared__ float tile[64][65];
    const int c0 = blockIdx.x * 64, r0 = blockIdx.y * 64;
    const int tid = threadIdx.x;
    const int lx = tid & 15;
    const int ly = tid >> 4;
    #pragma unroll
    for (int i = 0; i < 4; i++) {
        const int r = ly + i * 16;
        float4 v = *(const float4*)&in[(size_t)(r0 + r) * C + c0 + lx * 4];
        tile[lx * 4 + 0][r] = v.x;
        tile[lx * 4 + 1][r] = v.y;
        tile[lx * 4 + 2][r] = v.z;
        tile[lx * 4 + 3][r] = v.w;
    }
    __syncthreads();
    const int wx = tid & 31;
    const int wy = tid >> 5;
    #pragma unroll
    for (int i = 0; i < 8; i++) {
        const int c = wy + i * 8;
        *(__half2*)&out[(size_t)(c0 + c) * R + r0 + wx * 2] =
            __floats2half2_rn(tile[c][wx * 2], tile[c][wx * 2 + 1]);
    }
}

// ---------------------------------------------------------------------------
// Generic tiled transpose (half V)
// ---------------------------------------------------------------------------
template<typename Tin, typename Tout>
__global__ __launch_bounds__(256)
void transpose_kernel(const Tin* __restrict__ in, Tout* __restrict__ out, int R, int C)
{
    __shared__ float tile[32][33];
    const int c0 = blockIdx.x * 32, r0 = blockIdx.y * 32;
    const int x = threadIdx.x, y = threadIdx.y;
    #pragma unroll
    for (int i = 0; i < 32; i += 8)
        tile[y + i][x] = (float)in[(size_t)(r0 + y + i) * C + c0 + x];
    __syncthreads();
    #pragma unroll
    for (int i = 0; i < 32; i += 8)
        out[(size_t)(c0 + y + i) * R + r0 + x] = (Tout)tile[x][y + i];
}

// ---------------------------------------------------------------------------
// Fused RMSNorm + NeoX RoPE, warp-per-(t,h)
// ---------------------------------------------------------------------------
__global__ __launch_bounds__(128)
void normrope_kernel(const float* __restrict__ qkv,
                     const int*   __restrict__ positions,
                     const float* __restrict__ qw,
                     const float* __restrict__ kw,
                     __half* __restrict__ q_out,
                     __half* __restrict__ k_out,
                     __half* __restrict__ v_out)
{
    const int wg = blockIdx.x * 4 + (threadIdx.x >> 5);
    const int t = wg >> 4, h = wg & 15;
    const int lane = threadIdx.x & 31;
    const int pos = positions[t];
    const size_t row = (size_t)t * QKV_N;
    const size_t obase = (size_t)t * Q_SIZE + h * DH;

    float c[4], sn[4];
    #pragma unroll
    for (int i = 0; i < 4; i++) {
        const float fi = (float)(lane + 32 * i);
        const float fr = expf(-fi * (LN_THETA / 128.0f));
        sincosf((float)pos * fr, &sn[i], &c[i]);
    }

    #pragma unroll
    for (int sec = 0; sec < 3; sec++) {
        const size_t base = row + sec * Q_SIZE + h * DH;
        float x[8];
        #pragma unroll
        for (int i = 0; i < 8; i++) x[i] = qkv[base + lane + 32 * i];
        float ss = 0.0f;
        #pragma unroll
        for (int i = 0; i < 8; i++) ss += x[i] * x[i];
        #pragma unroll
        for (int off = 16; off > 0; off >>= 1) ss += __shfl_xor_sync(0xffffffffu, ss, off);
        const float rs = rsqrtf(ss * (1.0f / DH) + EPS);

        float v[8];
        #pragma unroll
        for (int i = 0; i < 8; i++) {
            float w = 1.0f;
            if (sec == 0) w = qw[lane + 32 * i];
            else if (sec == 1) w = kw[lane + 32 * i];
            v[i] = x[i] * rs * w;
        }
        if (sec < 2) {
            __half* outp = sec == 0 ? q_out : k_out;
            #pragma unroll
            for (int i = 0; i < 4; i++) {
                outp[obase + lane + 32 * i]       = __float2half(v[i] * c[i] - v[i + 4] * sn[i]);
                outp[obase + lane + 32 * i + 128] = __float2half(v[i + 4] * c[i] + v[i] * sn[i]);
            }
        } else {
            #pragma unroll
            for (int i = 0; i < 8; i++)
                v_out[obase + lane + 32 * i] = __float2half(v[i]);
        }
    }
}

// ---------------------------------------------------------------------------
// Launch
// ---------------------------------------------------------------------------
extern "C" void kernel_launch(void* const* d_in, const int* in_sizes, int n_in,
                              void* d_out, int out_size)
{
    const float* hidden    = (const float*)d_in[0];
    const int*   positions = (const int*)  d_in[1];
    const float* w_qkv     = (const float*)d_in[2];
    const float* w_o       = (const float*)d_in[3];
    const float* qw        = (const float*)d_in[4];
    const float* kw        = (const float*)d_in[5];
    float* out = (float*)d_out;

    __half *hid_h, *wqkv_h, *wo_h, *qh, *kh, *vh, *vth, *attn_h;
    float *qkv;
    cudaGetSymbolAddress((void**)&hid_h,  g_hidden_h);
    cudaGetSymbolAddress((void**)&wqkv_h, g_wqkv_h);
    cudaGetSymbolAddress((void**)&wo_h,   g_wo_h);
    cudaGetSymbolAddress((void**)&qkv,    g_qkv);
    cudaGetSymbolAddress((void**)&qh,     g_qh);
    cudaGetSymbolAddress((void**)&kh,     g_kh);
    cudaGetSymbolAddress((void**)&vh,     g_vh);
    cudaGetSymbolAddress((void**)&vth,    g_vth);
    cudaGetSymbolAddress((void**)&attn_h, g_attn_h);

    cudaFuncSetAttribute(h_gemm<false, false, false>, cudaFuncAttributeMaxDynamicSharedMemorySize, SMEM_BYTES);
    cudaFuncSetAttribute(flash_kernel, cudaFuncAttributeMaxDynamicSharedMemorySize, FLASH_SMEM);

    // 0) operand conversions / transposes
    convert_h_kernel<<<(T_SEQ * HID / 4 + 255) / 256, 256>>>(hidden, hid_h, T_SEQ * HID);
    transpose_f2h<<<dim3(QKV_N / 64, HID / 64), 256>>>(w_qkv, wqkv_h, HID, QKV_N);
    transpose_f2h<<<dim3(HID / 64,   HID / 64), 256>>>(w_o,   wo_h,   HID, HID);

    // 1) qkv = hidden @ w_qkv  (fp32 out for exact rmsnorm)
    h_gemm<false, false, false><<<dim3(QKV_N / BN, T_SEQ / BM, 1), 256, SMEM_BYTES>>>(
        hid_h, wqkv_h, qkv, T_SEQ, QKV_N, HID, HID, HID, QKV_N, 0, 0, 0);

    // 2) rmsnorm + rope -> fp16 q/k/v
    normrope_kernel<<<T_SEQ * NH / 4, 128>>>(qkv, positions, qw, kw, qh, kh, vh);

    // 2b) transpose V -> [NH*DH, T] fp16
    transpose_kernel<__half, __half><<<dim3((NH * DH) / 32, T_SEQ / 32), dim3(32, 8)>>>(vh, vth, T_SEQ, NH * DH);

    // 3) fused causal attention (full D per CTA) -> attn_h fp16
    flash_kernel<<<dim3(T_SEQ / FQM, NH, 1), 256, FLASH_SMEM>>>(qh, kh, vth, attn_h);

    // 4) out = attn @ w_o (fp32 out)
    h_gemm<false, false, false><<<dim3(HID / BN, T_SEQ / BM, 1), 256, SMEM_BYTES>>>(
        attn_h, wo_h, out, T_SEQ, HID, Q_SIZE, Q_SIZE, Q_SIZE, HID, 0, 0, 0);

    (void)in_sizes; (void)n_in; (void)out_size;
}

// round 13
// speedup vs baseline: 1.6291x; 1.0001x over previous
#include <cuda_runtime.h>
#include <cuda_fp16.h>
#include <math.h>
#include <float.h>
#include <cstdint>

// Problem constants
#define T_SEQ 2048
#define HID   4096
#define NH    16
#define DH    256
#define QKV_N (3 * NH * DH)      // 12288
#define Q_SIZE (NH * DH)         // 4096
#define EPS   1e-6f
#define LN_THETA 9.210340371976184f   // ln(10000)

// GEMM tile config (fp16 engine): CTA 128x128, warp 32x64, 8 warps, BK=64
#define BM 128
#define BN 128
#define BK 64
#define STRIDE 72
#define STAGES 3
#define STAGE_BYTES ((BM + BN) * STRIDE * 2)   // 36864
#define SMEM_BYTES (STAGES * STAGE_BYTES)      // 110592

// Flash v4: q-tile 128, kv-tile 64, 8 warps, FULL D=256, K/V double-buffered,
// V kept row-major [kv][d] and consumed via ldmatrix.trans.
#define FQM 128
#define FKV 64
#define QSTR 264                   // 256 + 8 pad (halfs) — used for Q, K, V tiles
#define FOFF_K0 (FQM * QSTR * 2)               // 67584
#define FK_BYTES (FKV * QSTR * 2)              // 33792
#define FOFF_V0 (FOFF_K0 + 2 * FK_BYTES)       // 135168
#define FV_BYTES (FKV * QSTR * 2)              // 33792
#define FLASH_SMEM (FOFF_V0 + 2 * FV_BYTES)    // 202752

// ---------------------------------------------------------------------------
// Scratch (static device globals)
// ---------------------------------------------------------------------------
__device__ __half g_hidden_h[(size_t)T_SEQ * HID];
__device__ __half g_wqkv_h[(size_t)QKV_N * HID];
__device__ __half g_wo_h[(size_t)HID * Q_SIZE];
__device__ float  g_qkv[(size_t)T_SEQ * QKV_N];
__device__ __half g_qh[(size_t)T_SEQ * NH * DH];
__device__ __half g_kh[(size_t)T_SEQ * NH * DH];
__device__ __half g_vh[(size_t)T_SEQ * NH * DH];
__device__ __half g_attn_h[(size_t)T_SEQ * NH * DH];

// ---------------------------------------------------------------------------
// PTX helpers
// ---------------------------------------------------------------------------
__device__ __forceinline__ uint32_t smem_u32(const void* p) {
    uint32_t a;
    asm("{ .reg .u64 t; cvta.to.shared.u64 t, %1; cvt.u32.u64 %0, t; }" : "=r"(a) : "l"(p));
    return a;
}
#define CP_ASYNC16(dst, src) \
    asm volatile("cp.async.cg.shared.global [%0], [%1], 16;" :: "r"(dst), "l"(src))
#define CP_COMMIT() asm volatile("cp.async.commit_group;" ::: "memory")
#define CP_WAIT(n)  asm volatile("cp.async.wait_group %0;" :: "n"(n) : "memory")

__device__ __forceinline__ void ldmx4(uint32_t* r, uint32_t addr) {
    asm volatile("ldmatrix.sync.aligned.m8n8.x4.shared.b16 {%0,%1,%2,%3}, [%4];"
        : "=r"(r[0]), "=r"(r[1]), "=r"(r[2]), "=r"(r[3]) : "r"(addr));
}
__device__ __forceinline__ void ldmx4_trans(uint32_t* r, uint32_t addr) {
    asm volatile("ldmatrix.sync.aligned.m8n8.x4.trans.shared.b16 {%0,%1,%2,%3}, [%4];"
        : "=r"(r[0]), "=r"(r[1]), "=r"(r[2]), "=r"(r[3]) : "r"(addr));
}
__device__ __forceinline__ void mma_f16(float* d, const uint32_t* a, const uint32_t* b) {
    asm volatile(
        "mma.sync.aligned.m16n8k16.row.col.f32.f16.f16.f32 "
        "{%0,%1,%2,%3}, {%4,%5,%6,%7}, {%8,%9}, {%0,%1,%2,%3};"
        : "+f"(d[0]), "+f"(d[1]), "+f"(d[2]), "+f"(d[3])
        : "r"(a[0]), "r"(a[1]), "r"(a[2]), "r"(a[3]), "r"(b[0]), "r"(b[1]));
}
__device__ __forceinline__ uint32_t h2pack(float a, float b) {
    __half2 h = __floats2half2_rn(a, b);
    return *(uint32_t*)&h;
}

// ---------------------------------------------------------------------------
// fp16 mma.sync GEMM (unchanged from R8)
// ---------------------------------------------------------------------------
template<bool CSKIP, bool CKLIM, bool HALF_OUT>
__global__ __launch_bounds__(256, 2)
void h_gemm(const __half* __restrict__ A, const __half* __restrict__ B, void* __restrict__ Cv,
            int M, int N, int K, int lda, int ldb, int ldc,
            long long bA, long long bB, long long bC)
{
    const int row0 = blockIdx.y * BM;
    const int col0 = blockIdx.x * BN;
    if (CSKIP && col0 >= row0 + BM) return;
    const int Keff = CKLIM ? min(K, row0 + BM) : K;
    const int nCh = Keff / BK;

    A += (long long)blockIdx.z * bA;
    B += (long long)blockIdx.z * bB;

    extern __shared__ char smem[];
    const uint32_t sbase = smem_u32(smem);

    const int tid = threadIdx.x;
    const int wid = tid >> 5, lane = tid & 31;
    const int g = lane >> 2, t4 = lane & 3;
    const int warpM = (wid & 3) * 32;
    const int warpN = (wid >> 2) * 64;
    const int lrow = lane & 7, lsel = lane >> 3;

    const uint32_t aoff = ((warpM + (lsel & 1) * 8 + lrow) * STRIDE + (lsel >> 1) * 8) * 2;
    const uint32_t boff = ((warpN + (lsel >> 1) * 8 + lrow) * STRIDE + (lsel & 1) * 8) * 2;

    float acc[2][8][4];
    #pragma unroll
    for (int i = 0; i < 2; i++)
        #pragma unroll
        for (int j = 0; j < 8; j++)
            #pragma unroll
            for (int q = 0; q < 4; q++) acc[i][j][q] = 0.0f;

    auto load_stage = [&](int st, int ch) {
        const uint32_t sA = sbase + st * STAGE_BYTES;
        const uint32_t sB = sA + BM * STRIDE * 2;
        const int k0 = ch * BK;
        #pragma unroll
        for (int i = 0; i < 4; i++) {
            int u = tid + i * 256;
            int r = u >> 3, cu = u & 7;
            CP_ASYNC16(sA + (r * STRIDE + cu * 8) * 2,
                       &A[(size_t)(row0 + r) * lda + k0 + cu * 8]);
        }
        #pragma unroll
        for (int i = 0; i < 4; i++) {
            int u = tid + i * 256;
            int r = u >> 3, cu = u & 7;
            CP_ASYNC16(sB + (r * STRIDE + cu * 8) * 2,
                       &B[(size_t)(col0 + r) * ldb + k0 + cu * 8]);
        }
    };

    auto compute_k16 = [&](uint32_t sA, uint32_t sB, int kk) {
        uint32_t a[2][4];
        ldmx4(a[0], sA + aoff + kk * 32);
        ldmx4(a[1], sA + aoff + 16 * STRIDE * 2 + kk * 32);
        uint32_t b[8][2];
        #pragma unroll
        for (int j = 0; j < 4; ++j) {
            uint32_t r[4];
            ldmx4(r, sB + boff + j * 16 * STRIDE * 2 + kk * 32);
            b[2 * j][0] = r[0]; b[2 * j][1] = r[1];
            b[2 * j + 1][0] = r[2]; b[2 * j + 1][1] = r[3];
        }
        #pragma unroll
        for (int nt = 0; nt < 8; ++nt) {
            mma_f16(acc[0][nt], a[0], b[nt]);
            mma_f16(acc[1][nt], a[1], b[nt]);
        }
    };

    #pragma unroll
    for (int p = 0; p < STAGES - 1; ++p) {
        if (p < nCh) load_stage(p, p);
        CP_COMMIT();
    }

    for (int c = 0; c < nCh; ++c) {
        CP_WAIT(STAGES - 2);
        __syncthreads();

        const uint32_t sA = sbase + (c % STAGES) * STAGE_BYTES;
        const uint32_t sB = sA + BM * STRIDE * 2;

        compute_k16(sA, sB, 0);
        if (c + STAGES - 1 < nCh) load_stage((c + STAGES - 1) % STAGES, c + STAGES - 1);
        CP_COMMIT();
        #pragma unroll
        for (int kk = 1; kk < 4; ++kk)
            compute_k16(sA, sB, kk);
    }

    #pragma unroll
    for (int mt = 0; mt < 2; mt++) {
        const int r0 = row0 + warpM + mt * 16 + g;
        #pragma unroll
        for (int nt = 0; nt < 8; nt++) {
            const int cc = col0 + warpN + nt * 8 + t4 * 2;
            if (HALF_OUT) {
                __half* C = (__half*)Cv + (long long)blockIdx.z * bC;
                *(__half2*)&C[(size_t)r0 * ldc + cc] =
                    __floats2half2_rn(acc[mt][nt][0], acc[mt][nt][1]);
                *(__half2*)&C[(size_t)(r0 + 8) * ldc + cc] =
                    __floats2half2_rn(acc[mt][nt][2], acc[mt][nt][3]);
            } else {
                float* C = (float*)Cv + (long long)blockIdx.z * bC;
                *(float2*)&C[(size_t)r0 * ldc + cc]       = make_float2(acc[mt][nt][0], acc[mt][nt][1]);
                *(float2*)&C[(size_t)(r0 + 8) * ldc + cc] = make_float2(acc[mt][nt][2], acc[mt][nt][3]);
            }
        }
    }
}

// ---------------------------------------------------------------------------
// Flash v4: q-tile 128, 8 warps, register-P, FULL D=256, V via ldmatrix.trans.
//   CTA = (128 q rows, head). Warp w owns rows w*16..w*16+15.
//   Q, K, V all stored row-major [rows][256/64->padded 264 halfs].
// ---------------------------------------------------------------------------
__global__ __launch_bounds__(256, 1)
void flash_kernel(const __half* __restrict__ Qg, const __half* __restrict__ Kg,
                  const __half* __restrict__ Vg, __half* __restrict__ Og)
{
    const int qtile = gridDim.x - 1 - blockIdx.x;   // longest work first
    const int q0 = qtile * FQM;
    const int h  = blockIdx.y;

    extern __shared__ char sm[];
    const uint32_t sb = smem_u32(sm);
    const uint32_t Qs = sb;

    const int tid = threadIdx.x;
    const int w = tid >> 5, lane = tid & 31;
    const int g = lane >> 2, t4 = lane & 3;
    const int lrow = lane & 7, lsel = lane >> 3;

    const __half* Qp = Qg + (size_t)h * DH;
    const __half* Kp = Kg + (size_t)h * DH;
    const __half* Vp = Vg + (size_t)h * DH;

    // Q tile (128 x 256): 4096 16B-units, 16 per thread
    #pragma unroll
    for (int i = 0; i < 16; i++) {
        int u = tid + i * 256;
        int r = u >> 5, cu = u & 31;
        CP_ASYNC16(Qs + (r * QSTR + cu * 8) * 2, Qp + (size_t)(q0 + r) * Q_SIZE + cu * 8);
    }

    auto load_kv = [&](int buf, int kv0) {
        const uint32_t Ks = sb + FOFF_K0 + buf * FK_BYTES;
        const uint32_t Vs = sb + FOFF_V0 + buf * FV_BYTES;
        #pragma unroll
        for (int i = 0; i < 8; i++) {           // K: 64 rows x 256 halfs
            int u = tid + i * 256;
            int r = u >> 5, cu = u & 31;
            CP_ASYNC16(Ks + (r * QSTR + cu * 8) * 2, Kp + (size_t)(kv0 + r) * Q_SIZE + cu * 8);
        }
        #pragma unroll
        for (int i = 0; i < 8; i++) {           // V: 64 rows x 256 halfs (row-major!)
            int u = tid + i * 256;
            int r = u >> 5, cu = u & 31;
            CP_ASYNC16(Vs + (r * QSTR + cu * 8) * 2, Vp + (size_t)(kv0 + r) * Q_SIZE + cu * 8);
        }
    };

    const uint32_t aoffQ = ((w * 16 + (lsel & 1) * 8 + lrow) * QSTR + (lsel >> 1) * 8) * 2;
    const uint32_t boffK = (((lsel >> 1) * 8 + lrow) * QSTR + (lsel & 1) * 8) * 2;
    // trans-V: lane L -> V row (lsel&1)*8 + lrow, d col (lsel>>1)*8
    const uint32_t boffV = (((lsel & 1) * 8 + lrow) * QSTR + (lsel >> 1) * 8) * 2;

    float m0 = -1e30f, m1 = -1e30f, l0 = 0.0f, l1 = 0.0f;
    float o[32][4];
    #pragma unroll
    for (int i = 0; i < 32; i++)
        #pragma unroll
        for (int q = 0; q < 4; q++) o[i][q] = 0.0f;

    const int nkv = 2 * qtile + 2;
    load_kv(0, 0);                  // prologue: Q + KV(0) in one group
    CP_COMMIT();

    for (int it = 0; it < nkv; ++it) {
        const int kv0 = it * FKV;
        CP_WAIT(0);                 // current buffer (and Q on it=0) resident
        __syncthreads();            // everyone done reading buf (it+1)&1 from iter it-1
        if (it + 1 < nkv) load_kv((it + 1) & 1, kv0 + FKV);
        CP_COMMIT();                // overlaps with compute below

        const uint32_t Ks = sb + FOFF_K0 + (it & 1) * FK_BYTES;
        const uint32_t Vs = sb + FOFF_V0 + (it & 1) * FV_BYTES;

        // warp fully above the diagonal? skip (no barriers inside body)
        if (kv0 > q0 + w * 16 + 15) continue;

        // S = Q K^T  (16 q rows x 64 kv cols per warp)
        float s[8][4];
        #pragma unroll
        for (int i = 0; i < 8; i++)
            #pragma unroll
            for (int q = 0; q < 4; q++) s[i][q] = 0.0f;
        #pragma unroll
        for (int ks = 0; ks < 16; ++ks) {
            uint32_t a[4];
            ldmx4(a, Qs + aoffQ + ks * 32);
            #pragma unroll
            for (int j = 0; j < 4; ++j) {
                uint32_t r4[4];
                ldmx4(r4, Ks + boffK + j * 16 * QSTR * 2 + ks * 32);
                mma_f16(s[2 * j], a, r4);
                mma_f16(s[2 * j + 1], a, r4 + 2);
            }
        }

        // causal mask if this tile can cross the diagonal for this warp
        if (kv0 + FKV - 1 > q0 + w * 16) {
            const int rowg = q0 + w * 16 + g;
            #pragma unroll
            for (int nt = 0; nt < 8; ++nt) {
                const int col = kv0 + nt * 8 + t4 * 2;
                if (col     > rowg)     s[nt][0] = -1e30f;
                if (col + 1 > rowg)     s[nt][1] = -1e30f;
                if (col     > rowg + 8) s[nt][2] = -1e30f;
                if (col + 1 > rowg + 8) s[nt][3] = -1e30f;
            }
        }

        // online softmax, rows g (r=0) and g+8 (r=1)
        #pragma unroll
        for (int r = 0; r < 2; ++r) {
            float mx = -1e30f;
            #pragma unroll
            for (int nt = 0; nt < 8; ++nt)
                mx = fmaxf(mx, fmaxf(s[nt][2 * r], s[nt][2 * r + 1]));
            mx = fmaxf(mx, __shfl_xor_sync(0xffffffffu, mx, 1));
            mx = fmaxf(mx, __shfl_xor_sync(0xffffffffu, mx, 2));
            const float mold = r ? m1 : m0;
            const float mnew = fmaxf(mold, mx);
            const float sc = __expf(mold - mnew);
            float sum = 0.0f;
            #pragma unroll
            for (int nt = 0; nt < 8; ++nt) {
                float p0 = __expf(s[nt][2 * r] - mnew);
                float p1 = __expf(s[nt][2 * r + 1] - mnew);
                s[nt][2 * r] = p0; s[nt][2 * r + 1] = p1;
                sum += p0 + p1;
            }
            sum += __shfl_xor_sync(0xffffffffu, sum, 1);
            sum += __shfl_xor_sync(0xffffffffu, sum, 2);
            if (r == 0) { l0 = l0 * sc + sum; m0 = mnew; }
            else        { l1 = l1 * sc + sum; m1 = mnew; }
            #pragma unroll
            for (int nt = 0; nt < 32; ++nt) {
                o[nt][2 * r]     *= sc;
                o[nt][2 * r + 1] *= sc;
            }
        }

        // O += P V with P straight from S registers; V^T frags via ldmatrix.trans
        #pragma unroll
        for (int ks2 = 0; ks2 < 4; ++ks2) {
            uint32_t a[4];
            a[0] = h2pack(s[2 * ks2][0],     s[2 * ks2][1]);
            a[1] = h2pack(s[2 * ks2][2],     s[2 * ks2][3]);
            a[2] = h2pack(s[2 * ks2 + 1][0], s[2 * ks2 + 1][1]);
            a[3] = h2pack(s[2 * ks2 + 1][2], s[2 * ks2 + 1][3]);
            const uint32_t vrow = Vs + boffV + ks2 * 16 * QSTR * 2;
            #pragma unroll
            for (int j = 0; j < 16; ++j) {      // full 256 d cols
                uint32_t r4[4];
                ldmx4_trans(r4, vrow + j * 32);
                mma_f16(o[2 * j], a, r4);
                mma_f16(o[2 * j + 1], a, r4 + 2);
            }
        }
    }

    const float i0 = 1.0f / l0, i1 = 1.0f / l1;
    const int tg = q0 + w * 16 + g;
    #pragma unroll
    for (int nt = 0; nt < 32; ++nt) {
        const int col = h * DH + nt * 8 + t4 * 2;
        *(__half2*)&Og[(size_t)tg * Q_SIZE + col] =
            __floats2half2_rn(o[nt][0] * i0, o[nt][1] * i0);
        *(__half2*)&Og[(size_t)(tg + 8) * Q_SIZE + col] =
            __floats2half2_rn(o[nt][2] * i1, o[nt][3] * i1);
    }
}

// ---------------------------------------------------------------------------
// Elementwise fp32 -> fp16 convert
// ---------------------------------------------------------------------------
__global__ __launch_bounds__(256)
void convert_h_kernel(const float* __restrict__ in, __half* __restrict__ out, int n)
{
    int i = (blockIdx.x * 256 + threadIdx.x) * 4;
    if (i < n) {
        float4 v = *(const float4*)&in[i];
        *(__half2*)&out[i]     = __floats2half2_rn(v.x, v.y);
        *(__half2*)&out[i + 2] = __floats2half2_rn(v.z, v.w);
    }
}

// ---------------------------------------------------------------------------
// Fast fp32->fp16 transpose, 64x64 tiles (weights)
// ---------------------------------------------------------------------------
__global__ __launch_bounds__(256)
void transpose_f2h(const float* __restrict__ in, __half* __restrict__ out, int R, int C)
{
    __shared__ float tile[64][65];
    const int c0 = blockIdx.x * 64, r0 = blockIdx.y * 64;
    const int tid = threadIdx.x;
    const int lx = tid & 15;
    const int ly = tid >> 4;
    #pragma unroll
    for (int i = 0; i < 4; i++) {
        const int r = ly + i * 16;
        float4 v = *(const float4*)&in[(size_t)(r0 + r) * C + c0 + lx * 4];
        tile[lx * 4 + 0][r] = v.x;
        tile[lx * 4 + 1][r] = v.y;
        tile[lx * 4 + 2][r] = v.z;
        tile[lx * 4 + 3][r] = v.w;
    }
    __syncthreads();
    const int wx = tid & 31;
    const int wy = tid >> 5;
    #pragma unroll
    for (int i = 0; i < 8; i++) {
        const int c = wy + i * 8;
        *(__half2*)&out[(size_t)(c0 + c) * R + r0 + wx * 2] =
            __floats2half2_rn(tile[c][wx * 2], tile[c][wx * 2 + 1]);
    }
}

// ---------------------------------------------------------------------------
// Fused RMSNorm + NeoX RoPE, warp-per-(t,h)
// ---------------------------------------------------------------------------
__global__ __launch_bounds__(128)
void normrope_kernel(const float* __restrict__ qkv,
                     const int*   __restrict__ positions,
                     const float* __restrict__ qw,
                     const float* __restrict__ kw,
                     __half* __restrict__ q_out,
                     __half* __restrict__ k_out,
                     __half* __restrict__ v_out)
{
    const int wg = blockIdx.x * 4 + (threadIdx.x >> 5);
    const int t = wg >> 4, h = wg & 15;
    const int lane = threadIdx.x & 31;
    const int pos = positions[t];
    const size_t row = (size_t)t * QKV_N;
    const size_t obase = (size_t)t * Q_SIZE + h * DH;

    float c[4], sn[4];
    #pragma unroll
    for (int i = 0; i < 4; i++) {
        const float fi = (float)(lane + 32 * i);
        const float fr = expf(-fi * (LN_THETA / 128.0f));
        sincosf((float)pos * fr, &sn[i], &c[i]);
    }

    #pragma unroll
    for (int sec = 0; sec < 3; sec++) {
        const size_t base = row + sec * Q_SIZE + h * DH;
        float x[8];
        #pragma unroll
        for (int i = 0; i < 8; i++) x[i] = qkv[base + lane + 32 * i];
        float ss = 0.0f;
        #pragma unroll
        for (int i = 0; i < 8; i++) ss += x[i] * x[i];
        #pragma unroll
        for (int off = 16; off > 0; off >>= 1) ss += __shfl_xor_sync(0xffffffffu, ss, off);
        const float rs = rsqrtf(ss * (1.0f / DH) + EPS);

        float v[8];
        #pragma unroll
        for (int i = 0; i < 8; i++) {
            float w = 1.0f;
            if (sec == 0) w = qw[lane + 32 * i];
            else if (sec == 1) w = kw[lane + 32 * i];
            v[i] = x[i] * rs * w;
        }
        if (sec < 2) {
            __half* outp = sec == 0 ? q_out : k_out;
            #pragma unroll
            for (int i = 0; i < 4; i++) {
                outp[obase + lane + 32 * i]       = __float2half(v[i] * c[i] - v[i + 4] * sn[i]);
                outp[obase + lane + 32 * i + 128] = __float2half(v[i + 4] * c[i] + v[i] * sn[i]);
            }
        } else {
            #pragma unroll
            for (int i = 0; i < 8; i++)
                v_out[obase + lane + 32 * i] = __float2half(v[i]);
        }
    }
}

// ---------------------------------------------------------------------------
// Launch
// ---------------------------------------------------------------------------
extern "C" void kernel_launch(void* const* d_in, const int* in_sizes, int n_in,
                              void* d_out, int out_size)
{
    const float* hidden    = (const float*)d_in[0];
    const int*   positions = (const int*)  d_in[1];
    const float* w_qkv     = (const float*)d_in[2];
    const float* w_o       = (const float*)d_in[3];
    const float* qw        = (const float*)d_in[4];
    const float* kw        = (const float*)d_in[5];
    float* out = (float*)d_out;

    __half *hid_h, *wqkv_h, *wo_h, *qh, *kh, *vh, *attn_h;
    float *qkv;
    cudaGetSymbolAddress((void**)&hid_h,  g_hidden_h);
    cudaGetSymbolAddress((void**)&wqkv_h, g_wqkv_h);
    cudaGetSymbolAddress((void**)&wo_h,   g_wo_h);
    cudaGetSymbolAddress((void**)&qkv,    g_qkv);
    cudaGetSymbolAddress((void**)&qh,     g_qh);
    cudaGetSymbolAddress((void**)&kh,     g_kh);
    cudaGetSymbolAddress((void**)&vh,     g_vh);
    cudaGetSymbolAddress((void**)&attn_h, g_attn_h);

    cudaFuncSetAttribute(h_gemm<false, false, false>, cudaFuncAttributeMaxDynamicSharedMemorySize, SMEM_BYTES);
    cudaFuncSetAttribute(flash_kernel, cudaFuncAttributeMaxDynamicSharedMemorySize, FLASH_SMEM);

    // 0) operand conversions / transposes (weights only — V needs no transpose now)
    convert_h_kernel<<<(T_SEQ * HID / 4 + 255) / 256, 256>>>(hidden, hid_h, T_SEQ * HID);
    transpose_f2h<<<dim3(QKV_N / 64, HID / 64), 256>>>(w_qkv, wqkv_h, HID, QKV_N);
    transpose_f2h<<<dim3(HID / 64,   HID / 64), 256>>>(w_o,   wo_h,   HID, HID);

    // 1) qkv = hidden @ w_qkv  (fp32 out for exact rmsnorm)
    h_gemm<false, false, false><<<dim3(QKV_N / BN, T_SEQ / BM, 1), 256, SMEM_BYTES>>>(
        hid_h, wqkv_h, qkv, T_SEQ, QKV_N, HID, HID, HID, QKV_N, 0, 0, 0);

    // 2) rmsnorm + rope -> fp16 q/k/v
    normrope_kernel<<<T_SEQ * NH / 4, 128>>>(qkv, positions, qw, kw, qh, kh, vh);

    // 3) fused causal attention (full D per CTA, row-major V) -> attn_h fp16
    flash_kernel<<<dim3(T_SEQ / FQM, NH, 1), 256, FLASH_SMEM>>>(qh, kh, vh, attn_h);

    // 4) out = attn @ w_o (fp32 out)
    h_gemm<false, false, false><<<dim3(HID / BN, T_SEQ / BM, 1), 256, SMEM_BYTES>>>(
        attn_h, wo_h, out, T_SEQ, HID, Q_SIZE, Q_SIZE, Q_SIZE, HID, 0, 0, 0);

    (void)in_sizes; (void)n_in; (void)out_size;
}